// round 3
// baseline (speedup 1.0000x reference)
#include <cuda_runtime.h>
#include <math.h>

#define H    16
#define HD   128
#define HHD  2048   // H*HD
#define SEQ  2048
#define NT   4096   // B*S tokens
#define DIM  2048
#define QR   1536
#define KVR  512
#define NOPE 96

// ---------------- scratch (device globals; no allocation allowed) ----------
__device__ float g_qlat[(size_t)NT * QR];
__device__ float g_q[(size_t)NT * HHD];
__device__ float g_kv[(size_t)NT * KVR];
__device__ float g_knope[(size_t)NT * QR];
__device__ float g_krope[(size_t)NT * KVR];
__device__ float g_k[(size_t)NT * HHD];
__device__ float g_v[(size_t)NT * HHD];
__device__ float g_attn[(size_t)NT * HHD];

// ---------------- generic fp32 SGEMM: C[M,N] = A[M,K] @ B[K,N] -------------
// 128x128 tile, BK=16, 256 threads, 8x8 per thread, float4 smem vectors.
#define BM 128
#define BN 128
#define BK 16

__global__ __launch_bounds__(256) void sgemm_kernel(
    const float* __restrict__ A, const float* __restrict__ B,
    float* __restrict__ C, int M, int N, int K) {
  __shared__ float As[BK][BM];  // transposed A tile
  __shared__ float Bs[BK][BN];
  const int tid = threadIdx.x;
  const int tx = tid & 15, ty = tid >> 4;
  const size_t bm = (size_t)blockIdx.y * BM;
  const size_t bn = (size_t)blockIdx.x * BN;
  const float* Ap = A + bm * (size_t)K;
  const float* Bp = B + bn;

  float acc[8][8];
#pragma unroll
  for (int i = 0; i < 8; i++)
#pragma unroll
    for (int j = 0; j < 8; j++) acc[i][j] = 0.f;

  for (int k0 = 0; k0 < K; k0 += BK) {
#pragma unroll
    for (int it = 0; it < 2; it++) {
      int idx = tid + it * 256;
      int ar = idx >> 2, ac = (idx & 3) << 2;
      float4 fa = *(const float4*)(Ap + (size_t)ar * K + k0 + ac);
      As[ac + 0][ar] = fa.x;
      As[ac + 1][ar] = fa.y;
      As[ac + 2][ar] = fa.z;
      As[ac + 3][ar] = fa.w;
      int br = idx >> 5, bc = (idx & 31) << 2;
      *(float4*)(&Bs[br][bc]) =
          *(const float4*)(Bp + (size_t)(k0 + br) * N + bc);
    }
    __syncthreads();
#pragma unroll
    for (int kk = 0; kk < BK; kk++) {
      float4 a0 = *(const float4*)(&As[kk][ty * 8]);
      float4 a1 = *(const float4*)(&As[kk][ty * 8 + 4]);
      float4 b0 = *(const float4*)(&Bs[kk][tx * 8]);
      float4 b1 = *(const float4*)(&Bs[kk][tx * 8 + 4]);
      float av[8] = {a0.x, a0.y, a0.z, a0.w, a1.x, a1.y, a1.z, a1.w};
      float bv[8] = {b0.x, b0.y, b0.z, b0.w, b1.x, b1.y, b1.z, b1.w};
#pragma unroll
      for (int i = 0; i < 8; i++)
#pragma unroll
        for (int j = 0; j < 8; j++) acc[i][j] += av[i] * bv[j];
    }
    __syncthreads();
  }

  float* Cp = C + (bm + (size_t)ty * 8) * N + bn + tx * 8;
#pragma unroll
  for (int i = 0; i < 8; i++) {
    *(float4*)(Cp + (size_t)i * N) =
        make_float4(acc[i][0], acc[i][1], acc[i][2], acc[i][3]);
    *(float4*)(Cp + (size_t)i * N + 4) =
        make_float4(acc[i][4], acc[i][5], acc[i][6], acc[i][7]);
  }
}

// ---------------- RoPE on q (in-place, cols [96,128) of each head) ---------
__global__ void rope_q_kernel(float* __restrict__ q,
                              const float* __restrict__ cosT,
                              const float* __restrict__ sinT) {
  int idx = blockIdx.x * blockDim.x + threadIdx.x;  // NT*H*16
  if (idx >= NT * H * 16) return;
  int pr = idx & 15;
  int h = (idx >> 4) & 15;
  int tok = idx >> 8;
  int t = tok & (SEQ - 1);
  float c = cosT[t * 16 + pr], s = sinT[t * 16 + pr];
  float2* p = (float2*)(q + (size_t)tok * HHD + h * HD + NOPE) + pr;
  float2 v = *p;
  *p = make_float2(v.x * c - v.y * s, v.x * s + v.y * c);
}

// ---------------- assemble k_final = [k_nope | rope(k_rope)] ---------------
__global__ void combine_k_kernel(const float* __restrict__ knope,
                                 const float* __restrict__ krope,
                                 float* __restrict__ kout,
                                 const float* __restrict__ cosT,
                                 const float* __restrict__ sinT) {
  int idx = blockIdx.x * blockDim.x + threadIdx.x;  // NT*H*64 (64 f2-pairs)
  if (idx >= NT * H * 64) return;
  int p = idx & 63;
  int h = (idx >> 6) & 15;
  int tok = idx >> 10;
  float2 v;
  if (p < 48) {
    v = *(const float2*)(knope + (size_t)tok * QR + h * NOPE + p * 2);
  } else {
    int j = p - 48;
    int t = tok & (SEQ - 1);
    float c = cosT[t * 16 + j], s = sinT[t * 16 + j];
    float2 r = *(const float2*)(krope + (size_t)tok * KVR + h * 32 + j * 2);
    v = make_float2(r.x * c - r.y * s, r.x * s + r.y * c);
  }
  *(float2*)(kout + (size_t)tok * HHD + h * HD + p * 2) = v;
}

// ---------------- causal flash attention, fp32, 64x64 tiles ----------------
#define QPAD 68
#define PPAD 68
#define FLASH_SMEM_FLOATS (128 * QPAD * 2 + 64 * 128 + 64 * PPAD + 192)

__global__ __launch_bounds__(256) void flash_kernel(
    const float* __restrict__ Q, const float* __restrict__ K,
    const float* __restrict__ V, float* __restrict__ O) {
  extern __shared__ float sm[];
  float* QsT = sm;                     // [128][QPAD] : [d][row]
  float* KsT = QsT + 128 * QPAD;       // [128][QPAD] : [d][key]
  float* Vs = KsT + 128 * QPAD;        // [64][128]   : [key][d]
  float* Ps = Vs + 64 * 128;           // [64][PPAD]
  float* rowm = Ps + 64 * PPAD;        // [64]
  float* rowl = rowm + 64;             // [64]
  float* rowsc = rowl + 64;            // [64]

  const int qb = blockIdx.x;
  const int bh = blockIdx.y;
  const int b = bh >> 4, h = bh & 15;
  const size_t base = ((size_t)b * SEQ) * HHD + (size_t)h * HD;
  const int tid = threadIdx.x;
  const int tx = tid & 15, ty = tid >> 4;

  // load Q tile (64 x 128), transposed into QsT
  const float* Qg = Q + base + (size_t)qb * 64 * HHD;
#pragma unroll
  for (int i = 0; i < 8; i++) {
    int idx = tid + i * 256;
    int r = idx >> 5, c4 = (idx & 31) << 2;
    float4 f = *(const float4*)(Qg + (size_t)r * HHD + c4);
    QsT[(c4 + 0) * QPAD + r] = f.x;
    QsT[(c4 + 1) * QPAD + r] = f.y;
    QsT[(c4 + 2) * QPAD + r] = f.z;
    QsT[(c4 + 3) * QPAD + r] = f.w;
  }
  if (tid < 64) {
    rowm[tid] = -1e30f;
    rowl[tid] = 0.f;
  }
  float acc[4][8];
#pragma unroll
  for (int i = 0; i < 4; i++)
#pragma unroll
    for (int j = 0; j < 8; j++) acc[i][j] = 0.f;
  __syncthreads();

  const float scale = 0.08838834764831843f;  // 1/sqrt(128)

  for (int kb = 0; kb <= qb; kb++) {
    const float* Kg = K + base + (size_t)kb * 64 * HHD;
    const float* Vg = V + base + (size_t)kb * 64 * HHD;
#pragma unroll
    for (int i = 0; i < 8; i++) {
      int idx = tid + i * 256;
      int r = idx >> 5, c4 = (idx & 31) << 2;
      float4 f = *(const float4*)(Kg + (size_t)r * HHD + c4);
      KsT[(c4 + 0) * QPAD + r] = f.x;
      KsT[(c4 + 1) * QPAD + r] = f.y;
      KsT[(c4 + 2) * QPAD + r] = f.z;
      KsT[(c4 + 3) * QPAD + r] = f.w;
      *(float4*)(Vs + r * 128 + c4) =
          *(const float4*)(Vg + (size_t)r * HHD + c4);
    }
    __syncthreads();

    // S = Q @ K^T : thread owns rows ty*4+i, cols tx*4+j
    float sacc[4][4];
#pragma unroll
    for (int i = 0; i < 4; i++)
#pragma unroll
      for (int j = 0; j < 4; j++) sacc[i][j] = 0.f;
#pragma unroll 4
    for (int d = 0; d < 128; d++) {
      float4 a = *(const float4*)(QsT + d * QPAD + ty * 4);
      float4 bq = *(const float4*)(KsT + d * QPAD + tx * 4);
      float av[4] = {a.x, a.y, a.z, a.w};
      float bv[4] = {bq.x, bq.y, bq.z, bq.w};
#pragma unroll
      for (int i = 0; i < 4; i++)
#pragma unroll
        for (int j = 0; j < 4; j++) sacc[i][j] += av[i] * bv[j];
    }
    const bool diag = (kb == qb);
#pragma unroll
    for (int i = 0; i < 4; i++) {
      int r = ty * 4 + i;
#pragma unroll
      for (int j = 0; j < 4; j++) {
        int c = tx * 4 + j;
        float v = sacc[i][j] * scale;
        if (diag && c > r) v = -1e30f;
        Ps[r * PPAD + c] = v;
      }
    }
    __syncthreads();

    // online softmax, one thread per row
    if (tid < 64) {
      int r = tid;
      float mo = rowm[r];
      float mn = mo;
#pragma unroll 8
      for (int c = 0; c < 64; c++) mn = fmaxf(mn, Ps[r * PPAD + c]);
      float corr = __expf(mo - mn);
      float ls = 0.f;
#pragma unroll 8
      for (int c = 0; c < 64; c++) {
        float pv = __expf(Ps[r * PPAD + c] - mn);
        Ps[r * PPAD + c] = pv;
        ls += pv;
      }
      rowl[r] = rowl[r] * corr + ls;
      rowm[r] = mn;
      rowsc[r] = corr;
    }
    __syncthreads();

    // rescale O, accumulate P @ V (thread rows ty*4+i, cols tx*8+j)
    float cr[4];
#pragma unroll
    for (int i = 0; i < 4; i++) cr[i] = rowsc[ty * 4 + i];
#pragma unroll
    for (int i = 0; i < 4; i++)
#pragma unroll
      for (int j = 0; j < 8; j++) acc[i][j] *= cr[i];

#pragma unroll 4
    for (int c = 0; c < 64; c++) {
      float pv[4];
#pragma unroll
      for (int i = 0; i < 4; i++) pv[i] = Ps[(ty * 4 + i) * PPAD + c];
      float4 v0 = *(const float4*)(Vs + c * 128 + tx * 8);
      float4 v1 = *(const float4*)(Vs + c * 128 + tx * 8 + 4);
      float vv[8] = {v0.x, v0.y, v0.z, v0.w, v1.x, v1.y, v1.z, v1.w};
#pragma unroll
      for (int i = 0; i < 4; i++)
#pragma unroll
        for (int j = 0; j < 8; j++) acc[i][j] += pv[i] * vv[j];
    }
    __syncthreads();
  }

  float* Og = O + base + (size_t)qb * 64 * HHD;
#pragma unroll
  for (int i = 0; i < 4; i++) {
    float inv = 1.f / rowl[ty * 4 + i];
    *(float4*)(Og + (size_t)(ty * 4 + i) * HHD + tx * 8) =
        make_float4(acc[i][0] * inv, acc[i][1] * inv, acc[i][2] * inv,
                    acc[i][3] * inv);
    *(float4*)(Og + (size_t)(ty * 4 + i) * HHD + tx * 8 + 4) =
        make_float4(acc[i][4] * inv, acc[i][5] * inv, acc[i][6] * inv,
                    acc[i][7] * inv);
  }
}

// ---------------- launch ----------------------------------------------------
extern "C" void kernel_launch(void* const* d_in, const int* in_sizes, int n_in,
                              void* d_out, int out_size) {
  const float* x = (const float*)d_in[0];
  const float* cosT = (const float*)d_in[1];
  const float* sinT = (const float*)d_in[2];
  const float* wq_down = (const float*)d_in[3];
  const float* wq_up = (const float*)d_in[4];
  const float* wkv_down = (const float*)d_in[5];
  const float* w_nope = (const float*)d_in[6];
  const float* w_rope = (const float*)d_in[7];
  const float* w_val = (const float*)d_in[8];
  const float* wo = (const float*)d_in[9];
  float* out = (float*)d_out;

  float *p_qlat, *p_q, *p_kv, *p_kn, *p_kr, *p_k, *p_v, *p_attn;
  cudaGetSymbolAddress((void**)&p_qlat, g_qlat);
  cudaGetSymbolAddress((void**)&p_q, g_q);
  cudaGetSymbolAddress((void**)&p_kv, g_kv);
  cudaGetSymbolAddress((void**)&p_kn, g_knope);
  cudaGetSymbolAddress((void**)&p_kr, g_krope);
  cudaGetSymbolAddress((void**)&p_k, g_k);
  cudaGetSymbolAddress((void**)&p_v, g_v);
  cudaGetSymbolAddress((void**)&p_attn, g_attn);

  const int flash_smem = FLASH_SMEM_FLOATS * (int)sizeof(float);
  cudaFuncSetAttribute(flash_kernel,
                       cudaFuncAttributeMaxDynamicSharedMemorySize, flash_smem);

  dim3 blk(256);
  // q = (x @ wq_down) @ wq_up
  sgemm_kernel<<<dim3(QR / BN, NT / BM), blk>>>(x, wq_down, p_qlat, NT, QR, DIM);
  sgemm_kernel<<<dim3(HHD / BN, NT / BM), blk>>>(p_qlat, wq_up, p_q, NT, HHD, QR);
  // kv latent and up-projections
  sgemm_kernel<<<dim3(KVR / BN, NT / BM), blk>>>(x, wkv_down, p_kv, NT, KVR, DIM);
  sgemm_kernel<<<dim3(QR / BN, NT / BM), blk>>>(p_kv, w_nope, p_kn, NT, QR, KVR);
  sgemm_kernel<<<dim3(KVR / BN, NT / BM), blk>>>(p_kv, w_rope, p_kr, NT, KVR, KVR);
  sgemm_kernel<<<dim3(HHD / BN, NT / BM), blk>>>(p_kv, w_val, p_v, NT, HHD, KVR);
  // rope + assemble K
  rope_q_kernel<<<(NT * H * 16) / 256, 256>>>(p_q, cosT, sinT);
  combine_k_kernel<<<(NT * H * 64) / 256, 256>>>(p_kn, p_kr, p_k, cosT, sinT);
  // attention
  flash_kernel<<<dim3(SEQ / 64, 2 * H), blk, flash_smem>>>(p_q, p_k, p_v, p_attn);
  // output projection
  sgemm_kernel<<<dim3(HHD / BN, NT / BM), blk>>>(p_attn, wo, out, NT, HHD, DIM);
}

// round 6
// speedup vs baseline: 1.5591x; 1.5591x over previous
#include <cuda_runtime.h>
#include <cuda_bf16.h>
#include <math.h>
#include <stdint.h>

#define H    16
#define HD   128
#define HHD  2048   // H*HD
#define SEQ  2048
#define NT   4096   // B*S tokens
#define DIM  2048
#define QR   1536
#define KVR  512
#define NOPE 96

// ---------------- fp32 scratch ----------------------------------------------
__device__ float g_qlat[(size_t)NT * QR];
__device__ float g_q[(size_t)NT * HHD];
__device__ float g_kv[(size_t)NT * KVR];
__device__ float g_knope[(size_t)NT * QR];
__device__ float g_krope[(size_t)NT * KVR];
__device__ float g_k[(size_t)NT * HHD];
__device__ float g_v[(size_t)NT * HHD];
__device__ float g_attn[(size_t)NT * HHD];

// ---------------- bf16 hi/lo scratch ----------------------------------------
__device__ __nv_bfloat16 g_x_h[(size_t)NT * DIM],  g_x_l[(size_t)NT * DIM];
__device__ __nv_bfloat16 g_ql_h[(size_t)NT * QR],  g_ql_l[(size_t)NT * QR];
__device__ __nv_bfloat16 g_kv_h[(size_t)NT * KVR], g_kv_l[(size_t)NT * KVR];
__device__ __nv_bfloat16 g_at_h[(size_t)NT * HHD], g_at_l[(size_t)NT * HHD];
// weights, pre-transposed to [N,K]
__device__ __nv_bfloat16 g_wqd_h[(size_t)QR * DIM],  g_wqd_l[(size_t)QR * DIM];
__device__ __nv_bfloat16 g_wqu_h[(size_t)HHD * QR],  g_wqu_l[(size_t)HHD * QR];
__device__ __nv_bfloat16 g_wkd_h[(size_t)KVR * DIM], g_wkd_l[(size_t)KVR * DIM];
__device__ __nv_bfloat16 g_wn_h[(size_t)QR * KVR],   g_wn_l[(size_t)QR * KVR];
__device__ __nv_bfloat16 g_wr_h[(size_t)KVR * KVR],  g_wr_l[(size_t)KVR * KVR];
__device__ __nv_bfloat16 g_wv_h[(size_t)HHD * KVR],  g_wv_l[(size_t)HHD * KVR];
__device__ __nv_bfloat16 g_wo_h[(size_t)DIM * HHD],  g_wo_l[(size_t)DIM * HHD];

// ---------------- helpers ----------------------------------------------------
__device__ __forceinline__ uint32_t smem_u32(const void* p) {
  uint32_t a;
  asm("{ .reg .u64 t; cvta.to.shared.u64 t, %1; cvt.u32.u64 %0, t; }"
      : "=r"(a) : "l"(p));
  return a;
}
__device__ __forceinline__ void cp16(uint32_t dst, const void* src) {
  asm volatile("cp.async.cg.shared.global [%0], [%1], 16;"
               :: "r"(dst), "l"(src) : "memory");
}
__device__ __forceinline__ void cp_commit() {
  asm volatile("cp.async.commit_group;" ::: "memory");
}
__device__ __forceinline__ void mma16816(float* c, const uint32_t* a,
                                         const uint32_t* b) {
  asm volatile(
      "mma.sync.aligned.m16n8k16.row.col.f32.bf16.bf16.f32 "
      "{%0,%1,%2,%3}, {%4,%5,%6,%7}, {%8,%9}, {%0,%1,%2,%3};"
      : "+f"(c[0]), "+f"(c[1]), "+f"(c[2]), "+f"(c[3])
      : "r"(a[0]), "r"(a[1]), "r"(a[2]), "r"(a[3]), "r"(b[0]), "r"(b[1]));
}

// ---------------- split / transpose-split conversions -----------------------
__global__ void split_kernel(const float* __restrict__ in,
                             __nv_bfloat16* __restrict__ hi,
                             __nv_bfloat16* __restrict__ lo, int n4) {
  int i = blockIdx.x * blockDim.x + threadIdx.x;
  if (i >= n4) return;
  float4 v = ((const float4*)in)[i];
  __nv_bfloat16 h0 = __float2bfloat16(v.x);
  __nv_bfloat16 h1 = __float2bfloat16(v.y);
  __nv_bfloat16 h2 = __float2bfloat16(v.z);
  __nv_bfloat16 h3 = __float2bfloat16(v.w);
  __nv_bfloat16 l0 = __float2bfloat16(v.x - __bfloat162float(h0));
  __nv_bfloat16 l1 = __float2bfloat16(v.y - __bfloat162float(h1));
  __nv_bfloat16 l2 = __float2bfloat16(v.z - __bfloat162float(h2));
  __nv_bfloat16 l3 = __float2bfloat16(v.w - __bfloat162float(h3));
  uint2 hp, lp;
  hp.x = ((uint32_t)__bfloat16_as_ushort(h1) << 16) | __bfloat16_as_ushort(h0);
  hp.y = ((uint32_t)__bfloat16_as_ushort(h3) << 16) | __bfloat16_as_ushort(h2);
  lp.x = ((uint32_t)__bfloat16_as_ushort(l1) << 16) | __bfloat16_as_ushort(l0);
  lp.y = ((uint32_t)__bfloat16_as_ushort(l3) << 16) | __bfloat16_as_ushort(l2);
  ((uint2*)hi)[i] = hp;
  ((uint2*)lo)[i] = lp;
}

// W[Kd,Nd] -> Th/Tl[Nd,Kd] (bf16 hi/lo)
__global__ void tsplit_kernel(const float* __restrict__ W,
                              __nv_bfloat16* __restrict__ Th,
                              __nv_bfloat16* __restrict__ Tl, int Kd, int Nd) {
  __shared__ float t[32][33];
  int n0 = blockIdx.x * 32, k0 = blockIdx.y * 32;
  int tx = threadIdx.x, ty = threadIdx.y;
#pragma unroll
  for (int i = 0; i < 32; i += 8)
    t[ty + i][tx] = W[(size_t)(k0 + ty + i) * Nd + n0 + tx];
  __syncthreads();
#pragma unroll
  for (int i = 0; i < 32; i += 8) {
    float v = t[tx][ty + i];
    size_t o = (size_t)(n0 + ty + i) * Kd + k0 + tx;
    __nv_bfloat16 h = __float2bfloat16(v);
    Th[o] = h;
    Tl[o] = __float2bfloat16(v - __bfloat162float(h));
  }
}

// ---------------- mma.sync bf16-split GEMM ----------------------------------
// C[M,N] = A[M,K] @ B[K,N]; A as hi/lo bf16 [M,K], B pre-transposed hi/lo
// bf16 [N,K]. Tile 128x128, BK=32, 256 threads (8 warps, 2x4 warp grid,
// 64x32 per warp). Double-buffered cp.async smem: rows padded to 40 halves
// (80B) for conflict-free fragment LDS.
// Stage layout (bytes): Ah 0, Al 10240, Bh 20480, Bl 30720; stride 40960.
#define MG_SMEM 81920

__device__ __forceinline__ void mg_load(uint32_t sb,
                                        const __nv_bfloat16* Ah,
                                        const __nv_bfloat16* Al,
                                        const __nv_bfloat16* Bh,
                                        const __nv_bfloat16* Bl,
                                        int K, int k0, int tid) {
#pragma unroll
  for (int i = 0; i < 2; i++) {
    int idx = tid + i * 256;
    int row = idx >> 2;
    int cw = (idx & 3) << 3;  // halves
    uint32_t d = sb + (uint32_t)(row * 80 + cw * 2);
    size_t g = (size_t)row * K + k0 + cw;
    cp16(d, Ah + g);
    cp16(d + 10240, Al + g);
    cp16(d + 20480, Bh + g);
    cp16(d + 30720, Bl + g);
  }
}

__global__ __launch_bounds__(256) void mma_gemm_kernel(
    const __nv_bfloat16* __restrict__ Ahi, const __nv_bfloat16* __restrict__ Alo,
    const __nv_bfloat16* __restrict__ Bhi, const __nv_bfloat16* __restrict__ Blo,
    float* __restrict__ C, int N, int K) {
  extern __shared__ __nv_bfloat16 smh[];
  const uint32_t sbase = smem_u32(smh);
  const int tid = threadIdx.x;
  const int warp = tid >> 5, lane = tid & 31;
  const int wm = warp >> 2, wn = warp & 3;
  const int g = lane >> 2, tg = lane & 3;
  const size_t brow = (size_t)blockIdx.y * 128;
  const size_t bcol = (size_t)blockIdx.x * 128;
  const __nv_bfloat16* Ah = Ahi + brow * K;
  const __nv_bfloat16* Al = Alo + brow * K;
  const __nv_bfloat16* Bh = Bhi + bcol * K;
  const __nv_bfloat16* Bl = Blo + bcol * K;

  float c[4][4][4];
#pragma unroll
  for (int mi = 0; mi < 4; mi++)
#pragma unroll
    for (int ni = 0; ni < 4; ni++)
#pragma unroll
      for (int k = 0; k < 4; k++) c[mi][ni][k] = 0.f;

  const int nk = K >> 5;
  mg_load(sbase, Ah, Al, Bh, Bl, K, 0, tid);
  cp_commit();

  for (int it = 0; it < nk; ++it) {
    if (it + 1 < nk) {
      mg_load(sbase + ((it + 1) & 1) * 40960, Ah, Al, Bh, Bl, K,
              (it + 1) << 5, tid);
      cp_commit();
      asm volatile("cp.async.wait_group 1;" ::: "memory");
    } else {
      asm volatile("cp.async.wait_group 0;" ::: "memory");
    }
    __syncthreads();
    const __nv_bfloat16* st = smh + (it & 1) * 20480;
#pragma unroll
    for (int kk = 0; kk < 2; kk++) {
      uint32_t ah[4][4], al[4][4];
#pragma unroll
      for (int mi = 0; mi < 4; mi++) {
        int r0 = (wm * 64 + mi * 16 + g) * 40 + kk * 16 + tg * 2;
        ah[mi][0] = *(const uint32_t*)(st + r0);
        ah[mi][1] = *(const uint32_t*)(st + r0 + 320);
        ah[mi][2] = *(const uint32_t*)(st + r0 + 8);
        ah[mi][3] = *(const uint32_t*)(st + r0 + 328);
        al[mi][0] = *(const uint32_t*)(st + 5120 + r0);
        al[mi][1] = *(const uint32_t*)(st + 5120 + r0 + 320);
        al[mi][2] = *(const uint32_t*)(st + 5120 + r0 + 8);
        al[mi][3] = *(const uint32_t*)(st + 5120 + r0 + 328);
      }
      uint32_t bh[4][2], bl[4][2];
#pragma unroll
      for (int ni = 0; ni < 4; ni++) {
        int r0 = 10240 + (wn * 32 + ni * 8 + g) * 40 + kk * 16 + tg * 2;
        bh[ni][0] = *(const uint32_t*)(st + r0);
        bh[ni][1] = *(const uint32_t*)(st + r0 + 8);
        bl[ni][0] = *(const uint32_t*)(st + 5120 + r0);
        bl[ni][1] = *(const uint32_t*)(st + 5120 + r0 + 8);
      }
#pragma unroll
      for (int mi = 0; mi < 4; mi++)
#pragma unroll
        for (int ni = 0; ni < 4; ni++) {
          mma16816(c[mi][ni], ah[mi], bh[ni]);
          mma16816(c[mi][ni], ah[mi], bl[ni]);
          mma16816(c[mi][ni], al[mi], bh[ni]);
        }
    }
    __syncthreads();
  }

#pragma unroll
  for (int mi = 0; mi < 4; mi++) {
    size_t row = brow + wm * 64 + mi * 16 + g;
#pragma unroll
    for (int ni = 0; ni < 4; ni++) {
      size_t col = bcol + wn * 32 + ni * 8 + tg * 2;
      *(float2*)(C + row * N + col) = make_float2(c[mi][ni][0], c[mi][ni][1]);
      *(float2*)(C + (row + 8) * N + col) =
          make_float2(c[mi][ni][2], c[mi][ni][3]);
    }
  }
}

// ---------------- RoPE on q (cols [96,128) of each head) --------------------
__global__ void rope_q_kernel(float* __restrict__ q,
                              const float* __restrict__ cosT,
                              const float* __restrict__ sinT) {
  int idx = blockIdx.x * blockDim.x + threadIdx.x;
  if (idx >= NT * H * 16) return;
  int pr = idx & 15;
  int h = (idx >> 4) & 15;
  int tok = idx >> 8;
  int t = tok & (SEQ - 1);
  float c = cosT[t * 16 + pr], s = sinT[t * 16 + pr];
  float2* p = (float2*)(q + (size_t)tok * HHD + h * HD + NOPE) + pr;
  float2 v = *p;
  *p = make_float2(v.x * c - v.y * s, v.x * s + v.y * c);
}

// ---------------- assemble k_final = [k_nope | rope(k_rope)] ----------------
__global__ void combine_k_kernel(const float* __restrict__ knope,
                                 const float* __restrict__ krope,
                                 float* __restrict__ kout,
                                 const float* __restrict__ cosT,
                                 const float* __restrict__ sinT) {
  int idx = blockIdx.x * blockDim.x + threadIdx.x;
  if (idx >= NT * H * 64) return;
  int p = idx & 63;
  int h = (idx >> 6) & 15;
  int tok = idx >> 10;
  float2 v;
  if (p < 48) {
    v = *(const float2*)(knope + (size_t)tok * QR + h * NOPE + p * 2);
  } else {
    int j = p - 48;
    int t = tok & (SEQ - 1);
    float c = cosT[t * 16 + j], s = sinT[t * 16 + j];
    float2 r = *(const float2*)(krope + (size_t)tok * KVR + h * 32 + j * 2);
    v = make_float2(r.x * c - r.y * s, r.x * s + r.y * c);
  }
  *(float2*)(kout + (size_t)tok * HHD + h * HD + p * 2) = v;
}

// ---------------- causal flash attention, fp32, 64x64 tiles -----------------
#define QPAD 68
#define PPAD 68
#define FLASH_SMEM_FLOATS (128 * QPAD * 2 + 64 * 128 + 64 * PPAD)

__global__ __launch_bounds__(256) void flash_kernel(
    const float* __restrict__ Q, const float* __restrict__ K,
    const float* __restrict__ V, float* __restrict__ O) {
  extern __shared__ float sm[];
  float* QsT = sm;                // [128][QPAD]
  float* KsT = QsT + 128 * QPAD;  // [128][QPAD]
  float* Vs = KsT + 128 * QPAD;   // [64][128]
  float* Ps = Vs + 64 * 128;      // [64][PPAD]

  const int qb = blockIdx.x;
  const int bh = blockIdx.y;
  const int b = bh >> 4, h = bh & 15;
  const size_t base = ((size_t)b * SEQ) * HHD + (size_t)h * HD;
  const int tid = threadIdx.x;
  const int tx = tid & 15, ty = tid >> 4;

  const float* Qg = Q + base + (size_t)qb * 64 * HHD;
#pragma unroll
  for (int i = 0; i < 8; i++) {
    int idx = tid + i * 256;
    int r = idx >> 5, c4 = (idx & 31) << 2;
    float4 f = *(const float4*)(Qg + (size_t)r * HHD + c4);
    QsT[(c4 + 0) * QPAD + r] = f.x;
    QsT[(c4 + 1) * QPAD + r] = f.y;
    QsT[(c4 + 2) * QPAD + r] = f.z;
    QsT[(c4 + 3) * QPAD + r] = f.w;
  }
  float m_i[4], l_i[4];
#pragma unroll
  for (int i = 0; i < 4; i++) { m_i[i] = -1e30f; l_i[i] = 0.f; }
  float acc[4][8];
#pragma unroll
  for (int i = 0; i < 4; i++)
#pragma unroll
    for (int j = 0; j < 8; j++) acc[i][j] = 0.f;
  __syncthreads();

  const float scale = 0.08838834764831843f;  // 1/sqrt(128)

  for (int kb = 0; kb <= qb; kb++) {
    const float* Kg = K + base + (size_t)kb * 64 * HHD;
    const float* Vg = V + base + (size_t)kb * 64 * HHD;
#pragma unroll
    for (int i = 0; i < 8; i++) {
      int idx = tid + i * 256;
      int r = idx >> 5, c4 = (idx & 31) << 2;
      float4 f = *(const float4*)(Kg + (size_t)r * HHD + c4);
      KsT[(c4 + 0) * QPAD + r] = f.x;
      KsT[(c4 + 1) * QPAD + r] = f.y;
      KsT[(c4 + 2) * QPAD + r] = f.z;
      KsT[(c4 + 3) * QPAD + r] = f.w;
      *(float4*)(Vs + r * 128 + c4) =
          *(const float4*)(Vg + (size_t)r * HHD + c4);
    }
    __syncthreads();

    // S = Q @ K^T
    float sacc[4][4];
#pragma unroll
    for (int i = 0; i < 4; i++)
#pragma unroll
      for (int j = 0; j < 4; j++) sacc[i][j] = 0.f;
#pragma unroll 4
    for (int d = 0; d < 128; d++) {
      float4 a = *(const float4*)(QsT + d * QPAD + ty * 4);
      float4 bq = *(const float4*)(KsT + d * QPAD + tx * 4);
      float av[4] = {a.x, a.y, a.z, a.w};
      float bv[4] = {bq.x, bq.y, bq.z, bq.w};
#pragma unroll
      for (int i = 0; i < 4; i++)
#pragma unroll
        for (int j = 0; j < 4; j++) sacc[i][j] += av[i] * bv[j];
    }
    const bool diag = (kb == qb);
    float mloc[4];
#pragma unroll
    for (int i = 0; i < 4; i++) {
      int r = ty * 4 + i;
#pragma unroll
      for (int j = 0; j < 4; j++) {
        int c = tx * 4 + j;
        float v = sacc[i][j] * scale;
        if (diag && c > r) v = -1e30f;
        sacc[i][j] = v;
      }
      mloc[i] = fmaxf(fmaxf(sacc[i][0], sacc[i][1]),
                      fmaxf(sacc[i][2], sacc[i][3]));
    }
#pragma unroll
    for (int o = 1; o < 16; o <<= 1)
#pragma unroll
      for (int i = 0; i < 4; i++)
        mloc[i] = fmaxf(mloc[i], __shfl_xor_sync(0xffffffffu, mloc[i], o));

    float corr[4], ls[4];
#pragma unroll
    for (int i = 0; i < 4; i++) {
      float mn = fmaxf(m_i[i], mloc[i]);
      corr[i] = __expf(m_i[i] - mn);
      m_i[i] = mn;
      float s0 = 0.f;
#pragma unroll
      for (int j = 0; j < 4; j++) {
        float p = __expf(sacc[i][j] - mn);
        sacc[i][j] = p;
        s0 += p;
      }
      ls[i] = s0;
    }
#pragma unroll
    for (int o = 1; o < 16; o <<= 1)
#pragma unroll
      for (int i = 0; i < 4; i++)
        ls[i] += __shfl_xor_sync(0xffffffffu, ls[i], o);
#pragma unroll
    for (int i = 0; i < 4; i++) l_i[i] = l_i[i] * corr[i] + ls[i];

#pragma unroll
    for (int i = 0; i < 4; i++)
      *(float4*)(&Ps[(ty * 4 + i) * PPAD + tx * 4]) =
          make_float4(sacc[i][0], sacc[i][1], sacc[i][2], sacc[i][3]);
    __syncthreads();

    // rescale O, accumulate P @ V
#pragma unroll
    for (int i = 0; i < 4; i++)
#pragma unroll
      for (int j = 0; j < 8; j++) acc[i][j] *= corr[i];

#pragma unroll 4
    for (int c = 0; c < 64; c++) {
      float pv[4];
#pragma unroll
      for (int i = 0; i < 4; i++) pv[i] = Ps[(ty * 4 + i) * PPAD + c];
      float4 v0 = *(const float4*)(Vs + c * 128 + tx * 8);
      float4 v1 = *(const float4*)(Vs + c * 128 + tx * 8 + 4);
      float vv[8] = {v0.x, v0.y, v0.z, v0.w, v1.x, v1.y, v1.z, v1.w};
#pragma unroll
      for (int i = 0; i < 4; i++)
#pragma unroll
        for (int j = 0; j < 8; j++) acc[i][j] += pv[i] * vv[j];
    }
    __syncthreads();
  }

  float* Og = O + base + (size_t)qb * 64 * HHD;
#pragma unroll
  for (int i = 0; i < 4; i++) {
    float inv = 1.f / l_i[i];
    *(float4*)(Og + (size_t)(ty * 4 + i) * HHD + tx * 8) =
        make_float4(acc[i][0] * inv, acc[i][1] * inv, acc[i][2] * inv,
                    acc[i][3] * inv);
    *(float4*)(Og + (size_t)(ty * 4 + i) * HHD + tx * 8 + 4) =
        make_float4(acc[i][4] * inv, acc[i][5] * inv, acc[i][6] * inv,
                    acc[i][7] * inv);
  }
}

// ---------------- launch -----------------------------------------------------
#define SYM(p, s)                          \
  do {                                     \
    void* _t;                              \
    cudaGetSymbolAddress(&_t, s);          \
    p = (decltype(p))_t;                   \
  } while (0)

extern "C" void kernel_launch(void* const* d_in, const int* in_sizes, int n_in,
                              void* d_out, int out_size) {
  const float* x = (const float*)d_in[0];
  const float* cosT = (const float*)d_in[1];
  const float* sinT = (const float*)d_in[2];
  const float* wq_down = (const float*)d_in[3];
  const float* wq_up = (const float*)d_in[4];
  const float* wkv_down = (const float*)d_in[5];
  const float* w_nope = (const float*)d_in[6];
  const float* w_rope = (const float*)d_in[7];
  const float* w_val = (const float*)d_in[8];
  const float* wo = (const float*)d_in[9];
  float* out = (float*)d_out;

  float *p_qlat, *p_q, *p_kv, *p_kn, *p_kr, *p_k, *p_v, *p_attn;
  SYM(p_qlat, g_qlat); SYM(p_q, g_q); SYM(p_kv, g_kv); SYM(p_kn, g_knope);
  SYM(p_kr, g_krope); SYM(p_k, g_k); SYM(p_v, g_v); SYM(p_attn, g_attn);

  __nv_bfloat16 *xh, *xl, *qlh, *qll, *kvh, *kvl, *ath, *atl;
  __nv_bfloat16 *wqdh, *wqdl, *wquh, *wqul, *wkdh, *wkdl;
  __nv_bfloat16 *wnh, *wnl, *wrh, *wrl, *wvh, *wvl, *woh, *wol;
  SYM(xh, g_x_h);  SYM(xl, g_x_l);  SYM(qlh, g_ql_h); SYM(qll, g_ql_l);
  SYM(kvh, g_kv_h); SYM(kvl, g_kv_l); SYM(ath, g_at_h); SYM(atl, g_at_l);
  SYM(wqdh, g_wqd_h); SYM(wqdl, g_wqd_l); SYM(wquh, g_wqu_h); SYM(wqul, g_wqu_l);
  SYM(wkdh, g_wkd_h); SYM(wkdl, g_wkd_l); SYM(wnh, g_wn_h);  SYM(wnl, g_wn_l);
  SYM(wrh, g_wr_h);  SYM(wrl, g_wr_l);  SYM(wvh, g_wv_h);  SYM(wvl, g_wv_l);
  SYM(woh, g_wo_h);  SYM(wol, g_wo_l);

  const int flash_smem = FLASH_SMEM_FLOATS * (int)sizeof(float);
  cudaFuncSetAttribute(flash_kernel,
                       cudaFuncAttributeMaxDynamicSharedMemorySize, flash_smem);
  cudaFuncSetAttribute(mma_gemm_kernel,
                       cudaFuncAttributeMaxDynamicSharedMemorySize, MG_SMEM);

  dim3 tsb(32, 8);
  // input/weight conversions
  split_kernel<<<(NT * DIM / 4) / 256, 256>>>(x, xh, xl, NT * DIM / 4);
  tsplit_kernel<<<dim3(QR / 32, DIM / 32), tsb>>>(wq_down, wqdh, wqdl, DIM, QR);
  tsplit_kernel<<<dim3(HHD / 32, QR / 32), tsb>>>(wq_up, wquh, wqul, QR, HHD);
  tsplit_kernel<<<dim3(KVR / 32, DIM / 32), tsb>>>(wkv_down, wkdh, wkdl, DIM, KVR);
  tsplit_kernel<<<dim3(QR / 32, KVR / 32), tsb>>>(w_nope, wnh, wnl, KVR, QR);
  tsplit_kernel<<<dim3(512 / 32, KVR / 32), tsb>>>(w_rope, wrh, wrl, KVR, 512);
  tsplit_kernel<<<dim3(HHD / 32, KVR / 32), tsb>>>(w_val, wvh, wvl, KVR, HHD);
  tsplit_kernel<<<dim3(DIM / 32, HHD / 32), tsb>>>(wo, woh, wol, HHD, DIM);

  // qlat = x @ wq_down ; q = qlat @ wq_up
  mma_gemm_kernel<<<dim3(QR / 128, NT / 128), 256, MG_SMEM>>>(
      xh, xl, wqdh, wqdl, p_qlat, QR, DIM);
  split_kernel<<<(NT * QR / 4) / 256, 256>>>(p_qlat, qlh, qll, NT * QR / 4);
  mma_gemm_kernel<<<dim3(HHD / 128, NT / 128), 256, MG_SMEM>>>(
      qlh, qll, wquh, wqul, p_q, HHD, QR);
  // kv latent + up-projections
  mma_gemm_kernel<<<dim3(KVR / 128, NT / 128), 256, MG_SMEM>>>(
      xh, xl, wkdh, wkdl, p_kv, KVR, DIM);
  split_kernel<<<(NT * KVR / 4) / 256, 256>>>(p_kv, kvh, kvl, NT * KVR / 4);
  mma_gemm_kernel<<<dim3(QR / 128, NT / 128), 256, MG_SMEM>>>(
      kvh, kvl, wnh, wnl, p_kn, QR, KVR);
  mma_gemm_kernel<<<dim3(512 / 128, NT / 128), 256, MG_SMEM>>>(
      kvh, kvl, wrh, wrl, p_kr, 512, KVR);
  mma_gemm_kernel<<<dim3(HHD / 128, NT / 128), 256, MG_SMEM>>>(
      kvh, kvl, wvh, wvl, p_v, HHD, KVR);
  // rope + assemble K
  rope_q_kernel<<<(NT * H * 16) / 256, 256>>>(p_q, cosT, sinT);
  combine_k_kernel<<<(NT * H * 64) / 256, 256>>>(p_kn, p_kr, p_k, cosT, sinT);
  // attention
  flash_kernel<<<dim3(SEQ / 64, 2 * H), 256, flash_smem>>>(p_q, p_k, p_v, p_attn);
  // output projection
  split_kernel<<<(NT * HHD / 4) / 256, 256>>>(p_attn, ath, atl, NT * HHD / 4);
  mma_gemm_kernel<<<dim3(DIM / 128, NT / 128), 256, MG_SMEM>>>(
      ath, atl, woh, wol, out, DIM, HHD);
}

// round 8
// speedup vs baseline: 2.4974x; 1.6018x over previous
#include <cuda_runtime.h>
#include <cuda_bf16.h>
#include <math.h>
#include <stdint.h>

#define H    16
#define HD   128
#define HHD  2048   // H*HD
#define SEQ  2048
#define NT   4096   // B*S tokens
#define DIM  2048
#define QR   1536
#define KVR  512
#define NOPE 96
#define BH   32     // B*H

// ---------------- fp32 scratch ----------------------------------------------
__device__ float g_qlat[(size_t)NT * QR];
__device__ float g_q[(size_t)NT * HHD];
__device__ float g_kv[(size_t)NT * KVR];
__device__ float g_knope[(size_t)NT * QR];
__device__ float g_krope[(size_t)NT * KVR];
__device__ float g_v[(size_t)NT * HHD];

// ---------------- bf16 hi/lo scratch ----------------------------------------
__device__ __nv_bfloat16 g_x_h[(size_t)NT * DIM],  g_x_l[(size_t)NT * DIM];
__device__ __nv_bfloat16 g_ql_h[(size_t)NT * QR],  g_ql_l[(size_t)NT * QR];
__device__ __nv_bfloat16 g_kv_h[(size_t)NT * KVR], g_kv_l[(size_t)NT * KVR];
__device__ __nv_bfloat16 g_at_h[(size_t)NT * HHD], g_at_l[(size_t)NT * HHD];
// attention operands, [BH][SEQ][HD] (Q,K) and [BH][HD][SEQ] (Vt)
__device__ __nv_bfloat16 g_qa_h[(size_t)BH * SEQ * HD], g_qa_l[(size_t)BH * SEQ * HD];
__device__ __nv_bfloat16 g_ka_h[(size_t)BH * SEQ * HD], g_ka_l[(size_t)BH * SEQ * HD];
__device__ __nv_bfloat16 g_vt_h[(size_t)BH * HD * SEQ], g_vt_l[(size_t)BH * HD * SEQ];
// weights, pre-transposed to [N,K]
__device__ __nv_bfloat16 g_wqd_h[(size_t)QR * DIM],  g_wqd_l[(size_t)QR * DIM];
__device__ __nv_bfloat16 g_wqu_h[(size_t)HHD * QR],  g_wqu_l[(size_t)HHD * QR];
__device__ __nv_bfloat16 g_wkd_h[(size_t)KVR * DIM], g_wkd_l[(size_t)KVR * DIM];
__device__ __nv_bfloat16 g_wn_h[(size_t)QR * KVR],   g_wn_l[(size_t)QR * KVR];
__device__ __nv_bfloat16 g_wr_h[(size_t)KVR * KVR],  g_wr_l[(size_t)KVR * KVR];
__device__ __nv_bfloat16 g_wv_h[(size_t)HHD * KVR],  g_wv_l[(size_t)HHD * KVR];
__device__ __nv_bfloat16 g_wo_h[(size_t)DIM * HHD],  g_wo_l[(size_t)DIM * HHD];

// ---------------- helpers ----------------------------------------------------
__device__ __forceinline__ uint32_t smem_u32(const void* p) {
  uint32_t a;
  asm("{ .reg .u64 t; cvta.to.shared.u64 t, %1; cvt.u32.u64 %0, t; }"
      : "=r"(a) : "l"(p));
  return a;
}
__device__ __forceinline__ void cp16(uint32_t dst, const void* src) {
  asm volatile("cp.async.cg.shared.global [%0], [%1], 16;"
               :: "r"(dst), "l"(src) : "memory");
}
__device__ __forceinline__ void cp_commit() {
  asm volatile("cp.async.commit_group;" ::: "memory");
}
__device__ __forceinline__ void mma16816(float* c, const uint32_t* a,
                                         const uint32_t* b) {
  asm volatile(
      "mma.sync.aligned.m16n8k16.row.col.f32.bf16.bf16.f32 "
      "{%0,%1,%2,%3}, {%4,%5,%6,%7}, {%8,%9}, {%0,%1,%2,%3};"
      : "+f"(c[0]), "+f"(c[1]), "+f"(c[2]), "+f"(c[3])
      : "r"(a[0]), "r"(a[1]), "r"(a[2]), "r"(a[3]), "r"(b[0]), "r"(b[1]));
}
__device__ __forceinline__ uint32_t pack2bf(float a, float b) {
  __nv_bfloat162 t;
  t.x = __float2bfloat16(a);
  t.y = __float2bfloat16(b);
  return *reinterpret_cast<uint32_t*>(&t);
}

// ---------------- split / transpose-split conversions -----------------------
__global__ void split_kernel(const float* __restrict__ in,
                             __nv_bfloat16* __restrict__ hi,
                             __nv_bfloat16* __restrict__ lo, int n4) {
  int i = blockIdx.x * blockDim.x + threadIdx.x;
  if (i >= n4) return;
  float4 v = ((const float4*)in)[i];
  __nv_bfloat16 h0 = __float2bfloat16(v.x);
  __nv_bfloat16 h1 = __float2bfloat16(v.y);
  __nv_bfloat16 h2 = __float2bfloat16(v.z);
  __nv_bfloat16 h3 = __float2bfloat16(v.w);
  __nv_bfloat16 l0 = __float2bfloat16(v.x - __bfloat162float(h0));
  __nv_bfloat16 l1 = __float2bfloat16(v.y - __bfloat162float(h1));
  __nv_bfloat16 l2 = __float2bfloat16(v.z - __bfloat162float(h2));
  __nv_bfloat16 l3 = __float2bfloat16(v.w - __bfloat162float(h3));
  uint2 hp, lp;
  hp.x = ((uint32_t)__bfloat16_as_ushort(h1) << 16) | __bfloat16_as_ushort(h0);
  hp.y = ((uint32_t)__bfloat16_as_ushort(h3) << 16) | __bfloat16_as_ushort(h2);
  lp.x = ((uint32_t)__bfloat16_as_ushort(l1) << 16) | __bfloat16_as_ushort(l0);
  lp.y = ((uint32_t)__bfloat16_as_ushort(l3) << 16) | __bfloat16_as_ushort(l2);
  ((uint2*)hi)[i] = hp;
  ((uint2*)lo)[i] = lp;
}

// W[Kd,Nd] -> Th/Tl[Nd,Kd] (bf16 hi/lo)
__global__ void tsplit_kernel(const float* __restrict__ W,
                              __nv_bfloat16* __restrict__ Th,
                              __nv_bfloat16* __restrict__ Tl, int Kd, int Nd) {
  __shared__ float t[32][33];
  int n0 = blockIdx.x * 32, k0 = blockIdx.y * 32;
  int tx = threadIdx.x, ty = threadIdx.y;
#pragma unroll
  for (int i = 0; i < 32; i += 8)
    t[ty + i][tx] = W[(size_t)(k0 + ty + i) * Nd + n0 + tx];
  __syncthreads();
#pragma unroll
  for (int i = 0; i < 32; i += 8) {
    float v = t[tx][ty + i];
    size_t o = (size_t)(n0 + ty + i) * Kd + k0 + tx;
    __nv_bfloat16 h = __float2bfloat16(v);
    Th[o] = h;
    Tl[o] = __float2bfloat16(v - __bfloat162float(h));
  }
}

// ---------------- mma.sync bf16-split GEMM (unchanged from R6) ---------------
#define MG_SMEM 81920

__device__ __forceinline__ void mg_load(uint32_t sb,
                                        const __nv_bfloat16* Ah,
                                        const __nv_bfloat16* Al,
                                        const __nv_bfloat16* Bh,
                                        const __nv_bfloat16* Bl,
                                        int K, int k0, int tid) {
#pragma unroll
  for (int i = 0; i < 2; i++) {
    int idx = tid + i * 256;
    int row = idx >> 2;
    int cw = (idx & 3) << 3;
    uint32_t d = sb + (uint32_t)(row * 80 + cw * 2);
    size_t g = (size_t)row * K + k0 + cw;
    cp16(d, Ah + g);
    cp16(d + 10240, Al + g);
    cp16(d + 20480, Bh + g);
    cp16(d + 30720, Bl + g);
  }
}

__global__ __launch_bounds__(256) void mma_gemm_kernel(
    const __nv_bfloat16* __restrict__ Ahi, const __nv_bfloat16* __restrict__ Alo,
    const __nv_bfloat16* __restrict__ Bhi, const __nv_bfloat16* __restrict__ Blo,
    float* __restrict__ C, int N, int K) {
  extern __shared__ __nv_bfloat16 smh[];
  const uint32_t sbase = smem_u32(smh);
  const int tid = threadIdx.x;
  const int warp = tid >> 5, lane = tid & 31;
  const int wm = warp >> 2, wn = warp & 3;
  const int g = lane >> 2, tg = lane & 3;
  const size_t brow = (size_t)blockIdx.y * 128;
  const size_t bcol = (size_t)blockIdx.x * 128;
  const __nv_bfloat16* Ah = Ahi + brow * K;
  const __nv_bfloat16* Al = Alo + brow * K;
  const __nv_bfloat16* Bh = Bhi + bcol * K;
  const __nv_bfloat16* Bl = Blo + bcol * K;

  float c[4][4][4];
#pragma unroll
  for (int mi = 0; mi < 4; mi++)
#pragma unroll
    for (int ni = 0; ni < 4; ni++)
#pragma unroll
      for (int k = 0; k < 4; k++) c[mi][ni][k] = 0.f;

  const int nk = K >> 5;
  mg_load(sbase, Ah, Al, Bh, Bl, K, 0, tid);
  cp_commit();

  for (int it = 0; it < nk; ++it) {
    if (it + 1 < nk) {
      mg_load(sbase + ((it + 1) & 1) * 40960, Ah, Al, Bh, Bl, K,
              (it + 1) << 5, tid);
      cp_commit();
      asm volatile("cp.async.wait_group 1;" ::: "memory");
    } else {
      asm volatile("cp.async.wait_group 0;" ::: "memory");
    }
    __syncthreads();
    const __nv_bfloat16* st = smh + (it & 1) * 20480;
#pragma unroll
    for (int kk = 0; kk < 2; kk++) {
      uint32_t ah[4][4], al[4][4];
#pragma unroll
      for (int mi = 0; mi < 4; mi++) {
        int r0 = (wm * 64 + mi * 16 + g) * 40 + kk * 16 + tg * 2;
        ah[mi][0] = *(const uint32_t*)(st + r0);
        ah[mi][1] = *(const uint32_t*)(st + r0 + 320);
        ah[mi][2] = *(const uint32_t*)(st + r0 + 8);
        ah[mi][3] = *(const uint32_t*)(st + r0 + 328);
        al[mi][0] = *(const uint32_t*)(st + 5120 + r0);
        al[mi][1] = *(const uint32_t*)(st + 5120 + r0 + 320);
        al[mi][2] = *(const uint32_t*)(st + 5120 + r0 + 8);
        al[mi][3] = *(const uint32_t*)(st + 5120 + r0 + 328);
      }
      uint32_t bh[4][2], bl[4][2];
#pragma unroll
      for (int ni = 0; ni < 4; ni++) {
        int r0 = 10240 + (wn * 32 + ni * 8 + g) * 40 + kk * 16 + tg * 2;
        bh[ni][0] = *(const uint32_t*)(st + r0);
        bh[ni][1] = *(const uint32_t*)(st + r0 + 8);
        bl[ni][0] = *(const uint32_t*)(st + 5120 + r0);
        bl[ni][1] = *(const uint32_t*)(st + 5120 + r0 + 8);
      }
#pragma unroll
      for (int mi = 0; mi < 4; mi++)
#pragma unroll
        for (int ni = 0; ni < 4; ni++) {
          mma16816(c[mi][ni], ah[mi], bh[ni]);
          mma16816(c[mi][ni], ah[mi], bl[ni]);
          mma16816(c[mi][ni], al[mi], bh[ni]);
        }
    }
    __syncthreads();
  }

#pragma unroll
  for (int mi = 0; mi < 4; mi++) {
    size_t row = brow + wm * 64 + mi * 16 + g;
#pragma unroll
    for (int ni = 0; ni < 4; ni++) {
      size_t col = bcol + wn * 32 + ni * 8 + tg * 2;
      *(float2*)(C + row * N + col) = make_float2(c[mi][ni][0], c[mi][ni][1]);
      *(float2*)(C + (row + 8) * N + col) =
          make_float2(c[mi][ni][2], c[mi][ni][3]);
    }
  }
}

// ---------------- q prep: rope + split + relayout to [BH][SEQ][HD] ----------
__global__ void q_prep_kernel(const float* __restrict__ q,
                              __nv_bfloat16* __restrict__ Qh,
                              __nv_bfloat16* __restrict__ Ql,
                              const float* __restrict__ cosT,
                              const float* __restrict__ sinT) {
  int idx = blockIdx.x * blockDim.x + threadIdx.x;  // BH*SEQ*64
  if (idx >= BH * SEQ * 64) return;
  int p = idx & 63;
  int s = (idx >> 6) & (SEQ - 1);
  int bh = idx >> 17;
  int b = bh >> 4, h = bh & 15;
  float2 v = *(const float2*)(q + ((size_t)(b * SEQ + s)) * HHD + h * HD + p * 2);
  if (p >= 48) {
    int j = p - 48;
    float cc = cosT[s * 16 + j], ss = sinT[s * 16 + j];
    v = make_float2(v.x * cc - v.y * ss, v.x * ss + v.y * cc);
  }
  float hx = __bfloat162float(__float2bfloat16(v.x));
  float hy = __bfloat162float(__float2bfloat16(v.y));
  size_t dst = ((size_t)bh * SEQ + s) * HD + p * 2;
  *(uint32_t*)(Qh + dst) = pack2bf(v.x, v.y);
  *(uint32_t*)(Ql + dst) = pack2bf(v.x - hx, v.y - hy);
}

// ---------------- k prep: assemble + rope + split to [BH][SEQ][HD] ----------
__global__ void k_prep_kernel(const float* __restrict__ knope,
                              const float* __restrict__ krope,
                              __nv_bfloat16* __restrict__ Kh,
                              __nv_bfloat16* __restrict__ Kl,
                              const float* __restrict__ cosT,
                              const float* __restrict__ sinT) {
  int idx = blockIdx.x * blockDim.x + threadIdx.x;  // BH*SEQ*64
  if (idx >= BH * SEQ * 64) return;
  int p = idx & 63;
  int s = (idx >> 6) & (SEQ - 1);
  int bh = idx >> 17;
  int b = bh >> 4, h = bh & 15;
  size_t tok = (size_t)(b * SEQ + s);
  float2 v;
  if (p < 48) {
    v = *(const float2*)(knope + tok * QR + h * NOPE + p * 2);
  } else {
    int j = p - 48;
    float cc = cosT[s * 16 + j], ss = sinT[s * 16 + j];
    float2 r = *(const float2*)(krope + tok * KVR + h * 32 + j * 2);
    v = make_float2(r.x * cc - r.y * ss, r.x * ss + r.y * cc);
  }
  float hx = __bfloat162float(__float2bfloat16(v.x));
  float hy = __bfloat162float(__float2bfloat16(v.y));
  size_t dst = ((size_t)bh * SEQ + s) * HD + p * 2;
  *(uint32_t*)(Kh + dst) = pack2bf(v.x, v.y);
  *(uint32_t*)(Kl + dst) = pack2bf(v.x - hx, v.y - hy);
}

// ---------------- v prep: transpose + split to [BH][HD][SEQ] ----------------
__global__ void vt_prep_kernel(const float* __restrict__ v,
                               __nv_bfloat16* __restrict__ Vh,
                               __nv_bfloat16* __restrict__ Vl) {
  __shared__ float t[32][33];
  int bh = blockIdx.z, b = bh >> 4, h = bh & 15;
  int s0 = blockIdx.x * 32, d0 = blockIdx.y * 32;
  int tx = threadIdx.x, ty = threadIdx.y;
#pragma unroll
  for (int i = 0; i < 32; i += 8)
    t[ty + i][tx] =
        v[((size_t)(b * SEQ) + s0 + ty + i) * HHD + h * HD + d0 + tx];
  __syncthreads();
#pragma unroll
  for (int i = 0; i < 32; i += 8) {
    float val = t[tx][ty + i];
    size_t o = ((size_t)bh * HD + d0 + ty + i) * SEQ + s0 + tx;
    __nv_bfloat16 hh = __float2bfloat16(val);
    Vh[o] = hh;
    Vl[o] = __float2bfloat16(val - __bfloat162float(hh));
  }
}

// ---------------- tensor-core flash attention --------------------------------
// Q tile 128, KV tile 64, 8 warps. All operands bf16 hi/lo, fp32 accum.
// smem (halves): Q_hi 0, Q_lo 17408 (128x136); stages at 34816 + s*35840:
//   K_hi 0 (64x136), K_lo 8704, Vt_hi 17408 (128x72), Vt_lo 26624.
#define FS_QL 17408
#define FS_K0 34816
#define FS_STG 35840
#define FS_KL 8704
#define FS_VH 17408
#define FLASH_MMA_SMEM 212992

__device__ __forceinline__ void flash_load_kv(
    uint32_t sb, const __nv_bfloat16* Kh, const __nv_bfloat16* Kl,
    const __nv_bfloat16* Vth, const __nv_bfloat16* Vtl, int kb, int stg,
    int tid) {
  uint32_t base = sb + (uint32_t)(FS_K0 + stg * FS_STG) * 2;
#pragma unroll
  for (int i = 0; i < 4; i++) {
    int idx = tid + i * 256;
    int r = idx >> 4, c = (idx & 15) << 3;
    uint32_t d = base + (uint32_t)(r * 136 + c) * 2;
    size_t gsrc = (size_t)(kb * 64 + r) * HD + c;
    cp16(d, Kh + gsrc);
    cp16(d + FS_KL * 2, Kl + gsrc);
  }
#pragma unroll
  for (int i = 0; i < 4; i++) {
    int idx = tid + i * 256;
    int r = idx >> 3, c = (idx & 7) << 3;
    uint32_t d = base + FS_VH * 2 + (uint32_t)(r * 72 + c) * 2;
    size_t gsrc = (size_t)r * SEQ + kb * 64 + c;
    cp16(d, Vth + gsrc);
    cp16(d + 9216 * 2, Vtl + gsrc);
  }
}

__global__ __launch_bounds__(256) void flash_mma_kernel(
    const __nv_bfloat16* __restrict__ Qh_, const __nv_bfloat16* __restrict__ Ql_,
    const __nv_bfloat16* __restrict__ Kh_, const __nv_bfloat16* __restrict__ Kl_,
    const __nv_bfloat16* __restrict__ Vh_, const __nv_bfloat16* __restrict__ Vl_,
    __nv_bfloat16* __restrict__ Oh, __nv_bfloat16* __restrict__ Ol) {
  extern __shared__ __nv_bfloat16 fs[];
  const uint32_t sb = smem_u32(fs);
  const int qb = blockIdx.x, bh = blockIdx.y;
  const int b = bh >> 4, h = bh & 15;
  const int tid = threadIdx.x, warp = tid >> 5, lane = tid & 31;
  const int g = lane >> 2, tg = lane & 3;
  const __nv_bfloat16* Qh = Qh_ + ((size_t)bh * SEQ + qb * 128) * HD;
  const __nv_bfloat16* Ql = Ql_ + ((size_t)bh * SEQ + qb * 128) * HD;
  const __nv_bfloat16* Kh = Kh_ + (size_t)bh * SEQ * HD;
  const __nv_bfloat16* Kl = Kl_ + (size_t)bh * SEQ * HD;
  const __nv_bfloat16* Vh = Vh_ + (size_t)bh * HD * SEQ;
  const __nv_bfloat16* Vl = Vl_ + (size_t)bh * HD * SEQ;

  // Q tile (hi+lo) -> smem
#pragma unroll
  for (int i = 0; i < 8; i++) {
    int idx = tid + i * 256;
    int r = idx >> 4, c = (idx & 15) << 3;
    uint32_t d = sb + (uint32_t)(r * 136 + c) * 2;
    cp16(d, Qh + (size_t)r * HD + c);
    cp16(d + FS_QL * 2, Ql + (size_t)r * HD + c);
  }
  flash_load_kv(sb, Kh, Kl, Vh, Vl, 0, 0, tid);
  cp_commit();

  float m0 = -1e30f, m1 = -1e30f, l0 = 0.f, l1 = 0.f;
  float o[16][4];
#pragma unroll
  for (int ni = 0; ni < 16; ni++)
#pragma unroll
    for (int k = 0; k < 4; k++) o[ni][k] = 0.f;

  const int nkb = 2 * qb + 2;
  const int rg0 = qb * 128 + warp * 16 + g;
  const int rg1 = rg0 + 8;
  const float scale = 0.08838834764831843f;

  for (int kb = 0; kb < nkb; kb++) {
    if (kb + 1 < nkb) {
      flash_load_kv(sb, Kh, Kl, Vh, Vl, kb + 1, (kb + 1) & 1, tid);
      cp_commit();
      asm volatile("cp.async.wait_group 1;" ::: "memory");
    } else {
      asm volatile("cp.async.wait_group 0;" ::: "memory");
    }
    __syncthreads();
    const __nv_bfloat16* Ks = fs + FS_K0 + (kb & 1) * FS_STG;
    const __nv_bfloat16* Vs = Ks + FS_VH;

    // S = Q @ K^T (hi/lo split)
    float c[8][4];
#pragma unroll
    for (int ni = 0; ni < 8; ni++)
#pragma unroll
      for (int k = 0; k < 4; k++) c[ni][k] = 0.f;
#pragma unroll
    for (int kk = 0; kk < 8; kk++) {
      const __nv_bfloat16* qp = fs + (warp * 16 + g) * 136 + kk * 16 + tg * 2;
      uint32_t ah[4], al[4];
      ah[0] = *(const uint32_t*)qp;
      ah[1] = *(const uint32_t*)(qp + 1088);
      ah[2] = *(const uint32_t*)(qp + 8);
      ah[3] = *(const uint32_t*)(qp + 1096);
      al[0] = *(const uint32_t*)(qp + FS_QL);
      al[1] = *(const uint32_t*)(qp + FS_QL + 1088);
      al[2] = *(const uint32_t*)(qp + FS_QL + 8);
      al[3] = *(const uint32_t*)(qp + FS_QL + 1096);
#pragma unroll
      for (int ni = 0; ni < 8; ni++) {
        const __nv_bfloat16* kp = Ks + (ni * 8 + g) * 136 + kk * 16 + tg * 2;
        uint32_t bh2[2], bl2[2];
        bh2[0] = *(const uint32_t*)kp;
        bh2[1] = *(const uint32_t*)(kp + 8);
        bl2[0] = *(const uint32_t*)(kp + FS_KL);
        bl2[1] = *(const uint32_t*)(kp + FS_KL + 8);
        mma16816(c[ni], ah, bh2);
        mma16816(c[ni], al, bh2);
        mma16816(c[ni], ah, bl2);
      }
    }

    // scale + causal mask + row max
    const bool msk = (kb >= 2 * qb);
    float mx0 = -1e30f, mx1 = -1e30f;
#pragma unroll
    for (int ni = 0; ni < 8; ni++) {
      int cg = kb * 64 + ni * 8 + tg * 2;
      float t0 = c[ni][0] * scale, t1 = c[ni][1] * scale;
      float t2 = c[ni][2] * scale, t3 = c[ni][3] * scale;
      if (msk) {
        if (cg > rg0) t0 = -1e30f;
        if (cg + 1 > rg0) t1 = -1e30f;
        if (cg > rg1) t2 = -1e30f;
        if (cg + 1 > rg1) t3 = -1e30f;
      }
      c[ni][0] = t0; c[ni][1] = t1; c[ni][2] = t2; c[ni][3] = t3;
      mx0 = fmaxf(mx0, fmaxf(t0, t1));
      mx1 = fmaxf(mx1, fmaxf(t2, t3));
    }
    mx0 = fmaxf(mx0, __shfl_xor_sync(0xffffffffu, mx0, 1));
    mx0 = fmaxf(mx0, __shfl_xor_sync(0xffffffffu, mx0, 2));
    mx1 = fmaxf(mx1, __shfl_xor_sync(0xffffffffu, mx1, 1));
    mx1 = fmaxf(mx1, __shfl_xor_sync(0xffffffffu, mx1, 2));

    float mn0 = fmaxf(m0, mx0), mn1 = fmaxf(m1, mx1);
    float corr0 = __expf(m0 - mn0), corr1 = __expf(m1 - mn1);
    m0 = mn0; m1 = mn1;
    float s0 = 0.f, s1 = 0.f;
#pragma unroll
    for (int ni = 0; ni < 8; ni++) {
      c[ni][0] = __expf(c[ni][0] - mn0);
      c[ni][1] = __expf(c[ni][1] - mn0);
      c[ni][2] = __expf(c[ni][2] - mn1);
      c[ni][3] = __expf(c[ni][3] - mn1);
      s0 += c[ni][0] + c[ni][1];
      s1 += c[ni][2] + c[ni][3];
    }
    s0 += __shfl_xor_sync(0xffffffffu, s0, 1);
    s0 += __shfl_xor_sync(0xffffffffu, s0, 2);
    s1 += __shfl_xor_sync(0xffffffffu, s1, 1);
    s1 += __shfl_xor_sync(0xffffffffu, s1, 2);
    l0 = l0 * corr0 + s0;
    l1 = l1 * corr1 + s1;

#pragma unroll
    for (int ni = 0; ni < 16; ni++) {
      o[ni][0] *= corr0; o[ni][1] *= corr0;
      o[ni][2] *= corr1; o[ni][3] *= corr1;
    }

    // O += P @ V (P from registers, hi/lo split)
#pragma unroll
    for (int kc = 0; kc < 4; kc++) {
      float p00 = c[2 * kc][0], p01 = c[2 * kc][1];
      float p02 = c[2 * kc][2], p03 = c[2 * kc][3];
      float p10 = c[2 * kc + 1][0], p11 = c[2 * kc + 1][1];
      float p12 = c[2 * kc + 1][2], p13 = c[2 * kc + 1][3];
      uint32_t ap[4], apl[4];
      ap[0] = pack2bf(p00, p01);
      ap[1] = pack2bf(p02, p03);
      ap[2] = pack2bf(p10, p11);
      ap[3] = pack2bf(p12, p13);
      float h00 = __bfloat162float(__float2bfloat16(p00));
      float h01 = __bfloat162float(__float2bfloat16(p01));
      float h02 = __bfloat162float(__float2bfloat16(p02));
      float h03 = __bfloat162float(__float2bfloat16(p03));
      float h10 = __bfloat162float(__float2bfloat16(p10));
      float h11 = __bfloat162float(__float2bfloat16(p11));
      float h12 = __bfloat162float(__float2bfloat16(p12));
      float h13 = __bfloat162float(__float2bfloat16(p13));
      apl[0] = pack2bf(p00 - h00, p01 - h01);
      apl[1] = pack2bf(p02 - h02, p03 - h03);
      apl[2] = pack2bf(p10 - h10, p11 - h11);
      apl[3] = pack2bf(p12 - h12, p13 - h13);
#pragma unroll
      for (int ni = 0; ni < 16; ni++) {
        const __nv_bfloat16* vp = Vs + (ni * 8 + g) * 72 + kc * 16 + tg * 2;
        uint32_t bv[2], bvl[2];
        bv[0] = *(const uint32_t*)vp;
        bv[1] = *(const uint32_t*)(vp + 8);
        bvl[0] = *(const uint32_t*)(vp + 9216);
        bvl[1] = *(const uint32_t*)(vp + 9216 + 8);
        mma16816(o[ni], ap, bv);
        mma16816(o[ni], apl, bv);
        mma16816(o[ni], ap, bvl);
      }
    }
    __syncthreads();
  }

  // epilogue: normalize, split to bf16 hi/lo, write [tok][HHD]
  const float inv0 = 1.f / l0, inv1 = 1.f / l1;
  const size_t row0 = (size_t)b * SEQ + qb * 128 + warp * 16 + g;
#pragma unroll
  for (int ni = 0; ni < 16; ni++) {
    int col = h * HD + ni * 8 + tg * 2;
    float v0 = o[ni][0] * inv0, v1 = o[ni][1] * inv0;
    float v2 = o[ni][2] * inv1, v3 = o[ni][3] * inv1;
    float h0 = __bfloat162float(__float2bfloat16(v0));
    float h1 = __bfloat162float(__float2bfloat16(v1));
    float h2 = __bfloat162float(__float2bfloat16(v2));
    float h3 = __bfloat162float(__float2bfloat16(v3));
    size_t i0 = row0 * HHD + col;
    size_t i1 = (row0 + 8) * HHD + col;
    *(uint32_t*)(Oh + i0) = pack2bf(v0, v1);
    *(uint32_t*)(Ol + i0) = pack2bf(v0 - h0, v1 - h1);
    *(uint32_t*)(Oh + i1) = pack2bf(v2, v3);
    *(uint32_t*)(Ol + i1) = pack2bf(v2 - h2, v3 - h3);
  }
}

// ---------------- launch -----------------------------------------------------
#define SYM(p, s)                          \
  do {                                     \
    void* _t;                              \
    cudaGetSymbolAddress(&_t, s);          \
    p = (decltype(p))_t;                   \
  } while (0)

extern "C" void kernel_launch(void* const* d_in, const int* in_sizes, int n_in,
                              void* d_out, int out_size) {
  const float* x = (const float*)d_in[0];
  const float* cosT = (const float*)d_in[1];
  const float* sinT = (const float*)d_in[2];
  const float* wq_down = (const float*)d_in[3];
  const float* wq_up = (const float*)d_in[4];
  const float* wkv_down = (const float*)d_in[5];
  const float* w_nope = (const float*)d_in[6];
  const float* w_rope = (const float*)d_in[7];
  const float* w_val = (const float*)d_in[8];
  const float* wo = (const float*)d_in[9];
  float* out = (float*)d_out;

  float *p_qlat, *p_q, *p_kv, *p_kn, *p_kr, *p_v;
  SYM(p_qlat, g_qlat); SYM(p_q, g_q); SYM(p_kv, g_kv); SYM(p_kn, g_knope);
  SYM(p_kr, g_krope); SYM(p_v, g_v);

  __nv_bfloat16 *xh, *xl, *qlh, *qll, *kvh, *kvl, *ath, *atl;
  __nv_bfloat16 *qah, *qal, *kah, *kal, *vth, *vtl;
  __nv_bfloat16 *wqdh, *wqdl, *wquh, *wqul, *wkdh, *wkdl;
  __nv_bfloat16 *wnh, *wnl, *wrh, *wrl, *wvh, *wvl, *woh, *wol;
  SYM(xh, g_x_h);  SYM(xl, g_x_l);  SYM(qlh, g_ql_h); SYM(qll, g_ql_l);
  SYM(kvh, g_kv_h); SYM(kvl, g_kv_l); SYM(ath, g_at_h); SYM(atl, g_at_l);
  SYM(qah, g_qa_h); SYM(qal, g_qa_l); SYM(kah, g_ka_h); SYM(kal, g_ka_l);
  SYM(vth, g_vt_h); SYM(vtl, g_vt_l);
  SYM(wqdh, g_wqd_h); SYM(wqdl, g_wqd_l); SYM(wquh, g_wqu_h); SYM(wqul, g_wqu_l);
  SYM(wkdh, g_wkd_h); SYM(wkdl, g_wkd_l); SYM(wnh, g_wn_h);  SYM(wnl, g_wn_l);
  SYM(wrh, g_wr_h);  SYM(wrl, g_wr_l);  SYM(wvh, g_wv_h);  SYM(wvl, g_wv_l);
  SYM(woh, g_wo_h);  SYM(wol, g_wo_l);

  cudaFuncSetAttribute(mma_gemm_kernel,
                       cudaFuncAttributeMaxDynamicSharedMemorySize, MG_SMEM);
  cudaFuncSetAttribute(flash_mma_kernel,
                       cudaFuncAttributeMaxDynamicSharedMemorySize,
                       FLASH_MMA_SMEM);

  dim3 tsb(32, 8);
  // input/weight conversions
  split_kernel<<<(NT * DIM / 4) / 256, 256>>>(x, xh, xl, NT * DIM / 4);
  tsplit_kernel<<<dim3(QR / 32, DIM / 32), tsb>>>(wq_down, wqdh, wqdl, DIM, QR);
  tsplit_kernel<<<dim3(HHD / 32, QR / 32), tsb>>>(wq_up, wquh, wqul, QR, HHD);
  tsplit_kernel<<<dim3(KVR / 32, DIM / 32), tsb>>>(wkv_down, wkdh, wkdl, DIM, KVR);
  tsplit_kernel<<<dim3(QR / 32, KVR / 32), tsb>>>(w_nope, wnh, wnl, KVR, QR);
  tsplit_kernel<<<dim3(512 / 32, KVR / 32), tsb>>>(w_rope, wrh, wrl, KVR, 512);
  tsplit_kernel<<<dim3(HHD / 32, KVR / 32), tsb>>>(w_val, wvh, wvl, KVR, HHD);
  tsplit_kernel<<<dim3(DIM / 32, HHD / 32), tsb>>>(wo, woh, wol, HHD, DIM);

  // q = (x @ wq_down) @ wq_up
  mma_gemm_kernel<<<dim3(QR / 128, NT / 128), 256, MG_SMEM>>>(
      xh, xl, wqdh, wqdl, p_qlat, QR, DIM);
  split_kernel<<<(NT * QR / 4) / 256, 256>>>(p_qlat, qlh, qll, NT * QR / 4);
  mma_gemm_kernel<<<dim3(HHD / 128, NT / 128), 256, MG_SMEM>>>(
      qlh, qll, wquh, wqul, p_q, HHD, QR);
  // kv latent + up-projections
  mma_gemm_kernel<<<dim3(KVR / 128, NT / 128), 256, MG_SMEM>>>(
      xh, xl, wkdh, wkdl, p_kv, KVR, DIM);
  split_kernel<<<(NT * KVR / 4) / 256, 256>>>(p_kv, kvh, kvl, NT * KVR / 4);
  mma_gemm_kernel<<<dim3(QR / 128, NT / 128), 256, MG_SMEM>>>(
      kvh, kvl, wnh, wnl, p_kn, QR, KVR);
  mma_gemm_kernel<<<dim3(512 / 128, NT / 128), 256, MG_SMEM>>>(
      kvh, kvl, wrh, wrl, p_kr, 512, KVR);
  mma_gemm_kernel<<<dim3(HHD / 128, NT / 128), 256, MG_SMEM>>>(
      kvh, kvl, wvh, wvl, p_v, HHD, KVR);

  // attention operand prep
  q_prep_kernel<<<(BH * SEQ * 64) / 256, 256>>>(p_q, qah, qal, cosT, sinT);
  k_prep_kernel<<<(BH * SEQ * 64) / 256, 256>>>(p_kn, p_kr, kah, kal, cosT,
                                                sinT);
  vt_prep_kernel<<<dim3(SEQ / 32, HD / 32, BH), tsb>>>(p_v, vth, vtl);

  // attention (writes bf16 hi/lo directly)
  flash_mma_kernel<<<dim3(SEQ / 128, BH), 256, FLASH_MMA_SMEM>>>(
      qah, qal, kah, kal, vth, vtl, ath, atl);

  // output projection
  mma_gemm_kernel<<<dim3(DIM / 128, NT / 128), 256, MG_SMEM>>>(
      ath, atl, woh, wol, out, DIM, HHD);
}

// round 10
// speedup vs baseline: 2.8354x; 1.1354x over previous
#include <cuda_runtime.h>
#include <cuda_bf16.h>
#include <math.h>
#include <stdint.h>

#define H    16
#define HD   128
#define HHD  2048   // H*HD
#define SEQ  2048
#define NT   4096   // B*S tokens
#define DIM  2048
#define QR   1536
#define KVR  512
#define NOPE 96
#define BH   32     // B*H
#define KVUP 4096   // QR + 512 + HHD

// ---------------- fp32 scratch ----------------------------------------------
__device__ float g_q[(size_t)NT * HHD];
__device__ float g_kvup[(size_t)NT * KVUP];  // [kn 0:1536 | kr 1536:2048 | v 2048:4096]

// ---------------- bf16 hi/lo scratch ----------------------------------------
__device__ __nv_bfloat16 g_x_h[(size_t)NT * DIM],  g_x_l[(size_t)NT * DIM];
__device__ __nv_bfloat16 g_qkv_h[(size_t)NT * 2048], g_qkv_l[(size_t)NT * 2048]; // [qlat|kv]
__device__ __nv_bfloat16 g_at_h[(size_t)NT * HHD], g_at_l[(size_t)NT * HHD];
// attention operands, [BH][SEQ][HD] (Q,K) and [BH][HD][SEQ] (Vt)
__device__ __nv_bfloat16 g_qa_h[(size_t)BH * SEQ * HD], g_qa_l[(size_t)BH * SEQ * HD];
__device__ __nv_bfloat16 g_ka_h[(size_t)BH * SEQ * HD], g_ka_l[(size_t)BH * SEQ * HD];
__device__ __nv_bfloat16 g_vt_h[(size_t)BH * HD * SEQ], g_vt_l[(size_t)BH * HD * SEQ];
// weights, pre-transposed to [N,K]; wA = [wq_down | wkv_down], wB = [wn|wr|wv]
__device__ __nv_bfloat16 g_wA_h[(size_t)2048 * DIM],  g_wA_l[(size_t)2048 * DIM];
__device__ __nv_bfloat16 g_wqu_h[(size_t)HHD * QR],   g_wqu_l[(size_t)HHD * QR];
__device__ __nv_bfloat16 g_wB_h[(size_t)KVUP * KVR],  g_wB_l[(size_t)KVUP * KVR];
__device__ __nv_bfloat16 g_wo_h[(size_t)DIM * HHD],   g_wo_l[(size_t)DIM * HHD];

// ---------------- helpers ----------------------------------------------------
__device__ __forceinline__ uint32_t smem_u32(const void* p) {
  uint32_t a;
  asm("{ .reg .u64 t; cvta.to.shared.u64 t, %1; cvt.u32.u64 %0, t; }"
      : "=r"(a) : "l"(p));
  return a;
}
__device__ __forceinline__ void cp16(uint32_t dst, const void* src) {
  asm volatile("cp.async.cg.shared.global [%0], [%1], 16;"
               :: "r"(dst), "l"(src) : "memory");
}
__device__ __forceinline__ void cp_commit() {
  asm volatile("cp.async.commit_group;" ::: "memory");
}
__device__ __forceinline__ void mma16816(float* c, const uint32_t* a,
                                         const uint32_t* b) {
  asm volatile(
      "mma.sync.aligned.m16n8k16.row.col.f32.bf16.bf16.f32 "
      "{%0,%1,%2,%3}, {%4,%5,%6,%7}, {%8,%9}, {%0,%1,%2,%3};"
      : "+f"(c[0]), "+f"(c[1]), "+f"(c[2]), "+f"(c[3])
      : "r"(a[0]), "r"(a[1]), "r"(a[2]), "r"(a[3]), "r"(b[0]), "r"(b[1]));
}
__device__ __forceinline__ uint32_t pack2bf(float a, float b) {
  __nv_bfloat162 t;
  t.x = __float2bfloat16(a);
  t.y = __float2bfloat16(b);
  return *reinterpret_cast<uint32_t*>(&t);
}

// ---------------- split / transpose-split conversions -----------------------
__global__ void split_kernel(const float* __restrict__ in,
                             __nv_bfloat16* __restrict__ hi,
                             __nv_bfloat16* __restrict__ lo, int n4) {
  int i = blockIdx.x * blockDim.x + threadIdx.x;
  if (i >= n4) return;
  float4 v = ((const float4*)in)[i];
  __nv_bfloat16 h0 = __float2bfloat16(v.x);
  __nv_bfloat16 h1 = __float2bfloat16(v.y);
  __nv_bfloat16 h2 = __float2bfloat16(v.z);
  __nv_bfloat16 h3 = __float2bfloat16(v.w);
  __nv_bfloat16 l0 = __float2bfloat16(v.x - __bfloat162float(h0));
  __nv_bfloat16 l1 = __float2bfloat16(v.y - __bfloat162float(h1));
  __nv_bfloat16 l2 = __float2bfloat16(v.z - __bfloat162float(h2));
  __nv_bfloat16 l3 = __float2bfloat16(v.w - __bfloat162float(h3));
  uint2 hp, lp;
  hp.x = ((uint32_t)__bfloat16_as_ushort(h1) << 16) | __bfloat16_as_ushort(h0);
  hp.y = ((uint32_t)__bfloat16_as_ushort(h3) << 16) | __bfloat16_as_ushort(h2);
  lp.x = ((uint32_t)__bfloat16_as_ushort(l1) << 16) | __bfloat16_as_ushort(l0);
  lp.y = ((uint32_t)__bfloat16_as_ushort(l3) << 16) | __bfloat16_as_ushort(l2);
  ((uint2*)hi)[i] = hp;
  ((uint2*)lo)[i] = lp;
}

// W[Kd,Nd] -> Th/Tl[Nd,Kd] (bf16 hi/lo)
__global__ void tsplit_kernel(const float* __restrict__ W,
                              __nv_bfloat16* __restrict__ Th,
                              __nv_bfloat16* __restrict__ Tl, int Kd, int Nd) {
  __shared__ float t[32][33];
  int n0 = blockIdx.x * 32, k0 = blockIdx.y * 32;
  int tx = threadIdx.x, ty = threadIdx.y;
#pragma unroll
  for (int i = 0; i < 32; i += 8)
    t[ty + i][tx] = W[(size_t)(k0 + ty + i) * Nd + n0 + tx];
  __syncthreads();
#pragma unroll
  for (int i = 0; i < 32; i += 8) {
    float v = t[tx][ty + i];
    size_t o = (size_t)(n0 + ty + i) * Kd + k0 + tx;
    __nv_bfloat16 h = __float2bfloat16(v);
    Th[o] = h;
    Tl[o] = __float2bfloat16(v - __bfloat162float(h));
  }
}

// ---------------- mma.sync bf16-split GEMM ----------------------------------
// C[M,N] = A[M,K] @ B[K,N]; A hi/lo bf16 [M,K] (row stride lda), B [N,K]
// (row stride ldb). Output: fp32 Cf, or bf16 hi/lo (Chi/Clo) if split_out.
#define MG_SMEM 81920

__device__ __forceinline__ void mg_load(uint32_t sb,
                                        const __nv_bfloat16* Ah,
                                        const __nv_bfloat16* Al,
                                        const __nv_bfloat16* Bh,
                                        const __nv_bfloat16* Bl,
                                        int lda, int ldb, int k0, int tid) {
#pragma unroll
  for (int i = 0; i < 2; i++) {
    int idx = tid + i * 256;
    int row = idx >> 2;
    int cw = (idx & 3) << 3;
    uint32_t d = sb + (uint32_t)(row * 80 + cw * 2);
    size_t ga = (size_t)row * lda + k0 + cw;
    size_t gb = (size_t)row * ldb + k0 + cw;
    cp16(d, Ah + ga);
    cp16(d + 10240, Al + ga);
    cp16(d + 20480, Bh + gb);
    cp16(d + 30720, Bl + gb);
  }
}

__global__ __launch_bounds__(256) void mma_gemm_kernel(
    const __nv_bfloat16* __restrict__ Ahi, const __nv_bfloat16* __restrict__ Alo,
    const __nv_bfloat16* __restrict__ Bhi, const __nv_bfloat16* __restrict__ Blo,
    float* __restrict__ Cf, __nv_bfloat16* __restrict__ Chi,
    __nv_bfloat16* __restrict__ Clo, int N, int K, int lda, int ldb,
    int split_out) {
  extern __shared__ __nv_bfloat16 smh[];
  const uint32_t sbase = smem_u32(smh);
  const int tid = threadIdx.x;
  const int warp = tid >> 5, lane = tid & 31;
  const int wm = warp >> 2, wn = warp & 3;
  const int g = lane >> 2, tg = lane & 3;
  const size_t brow = (size_t)blockIdx.y * 128;
  const size_t bcol = (size_t)blockIdx.x * 128;
  const __nv_bfloat16* Ah = Ahi + brow * lda;
  const __nv_bfloat16* Al = Alo + brow * lda;
  const __nv_bfloat16* Bh = Bhi + bcol * ldb;
  const __nv_bfloat16* Bl = Blo + bcol * ldb;

  float c[4][4][4];
#pragma unroll
  for (int mi = 0; mi < 4; mi++)
#pragma unroll
    for (int ni = 0; ni < 4; ni++)
#pragma unroll
      for (int k = 0; k < 4; k++) c[mi][ni][k] = 0.f;

  const int nk = K >> 5;
  mg_load(sbase, Ah, Al, Bh, Bl, lda, ldb, 0, tid);
  cp_commit();

  for (int it = 0; it < nk; ++it) {
    if (it + 1 < nk) {
      mg_load(sbase + ((it + 1) & 1) * 40960, Ah, Al, Bh, Bl, lda, ldb,
              (it + 1) << 5, tid);
      cp_commit();
      asm volatile("cp.async.wait_group 1;" ::: "memory");
    } else {
      asm volatile("cp.async.wait_group 0;" ::: "memory");
    }
    __syncthreads();
    const __nv_bfloat16* st = smh + (it & 1) * 20480;
#pragma unroll
    for (int kk = 0; kk < 2; kk++) {
      uint32_t ah[4][4], al[4][4];
#pragma unroll
      for (int mi = 0; mi < 4; mi++) {
        int r0 = (wm * 64 + mi * 16 + g) * 40 + kk * 16 + tg * 2;
        ah[mi][0] = *(const uint32_t*)(st + r0);
        ah[mi][1] = *(const uint32_t*)(st + r0 + 320);
        ah[mi][2] = *(const uint32_t*)(st + r0 + 8);
        ah[mi][3] = *(const uint32_t*)(st + r0 + 328);
        al[mi][0] = *(const uint32_t*)(st + 5120 + r0);
        al[mi][1] = *(const uint32_t*)(st + 5120 + r0 + 320);
        al[mi][2] = *(const uint32_t*)(st + 5120 + r0 + 8);
        al[mi][3] = *(const uint32_t*)(st + 5120 + r0 + 328);
      }
      uint32_t bh[4][2], bl[4][2];
#pragma unroll
      for (int ni = 0; ni < 4; ni++) {
        int r0 = 10240 + (wn * 32 + ni * 8 + g) * 40 + kk * 16 + tg * 2;
        bh[ni][0] = *(const uint32_t*)(st + r0);
        bh[ni][1] = *(const uint32_t*)(st + r0 + 8);
        bl[ni][0] = *(const uint32_t*)(st + 5120 + r0);
        bl[ni][1] = *(const uint32_t*)(st + 5120 + r0 + 8);
      }
#pragma unroll
      for (int mi = 0; mi < 4; mi++)
#pragma unroll
        for (int ni = 0; ni < 4; ni++) {
          mma16816(c[mi][ni], ah[mi], bh[ni]);
          mma16816(c[mi][ni], ah[mi], bl[ni]);
          mma16816(c[mi][ni], al[mi], bh[ni]);
        }
    }
    __syncthreads();
  }

#pragma unroll
  for (int mi = 0; mi < 4; mi++) {
    size_t row = brow + wm * 64 + mi * 16 + g;
#pragma unroll
    for (int ni = 0; ni < 4; ni++) {
      size_t col = bcol + wn * 32 + ni * 8 + tg * 2;
      if (split_out) {
        float v0 = c[mi][ni][0], v1 = c[mi][ni][1];
        float v2 = c[mi][ni][2], v3 = c[mi][ni][3];
        float h0 = __bfloat162float(__float2bfloat16(v0));
        float h1 = __bfloat162float(__float2bfloat16(v1));
        float h2 = __bfloat162float(__float2bfloat16(v2));
        float h3 = __bfloat162float(__float2bfloat16(v3));
        *(uint32_t*)(Chi + row * N + col) = pack2bf(v0, v1);
        *(uint32_t*)(Clo + row * N + col) = pack2bf(v0 - h0, v1 - h1);
        *(uint32_t*)(Chi + (row + 8) * N + col) = pack2bf(v2, v3);
        *(uint32_t*)(Clo + (row + 8) * N + col) = pack2bf(v2 - h2, v3 - h3);
      } else {
        *(float2*)(Cf + row * N + col) =
            make_float2(c[mi][ni][0], c[mi][ni][1]);
        *(float2*)(Cf + (row + 8) * N + col) =
            make_float2(c[mi][ni][2], c[mi][ni][3]);
      }
    }
  }
}

// ---------------- q prep: rope + split + relayout to [BH][SEQ][HD] ----------
__global__ void q_prep_kernel(const float* __restrict__ q,
                              __nv_bfloat16* __restrict__ Qh,
                              __nv_bfloat16* __restrict__ Ql,
                              const float* __restrict__ cosT,
                              const float* __restrict__ sinT) {
  int idx = blockIdx.x * blockDim.x + threadIdx.x;  // BH*SEQ*64
  if (idx >= BH * SEQ * 64) return;
  int p = idx & 63;
  int s = (idx >> 6) & (SEQ - 1);
  int bh = idx >> 17;
  int b = bh >> 4, h = bh & 15;
  float2 v = *(const float2*)(q + ((size_t)(b * SEQ + s)) * HHD + h * HD + p * 2);
  if (p >= 48) {
    int j = p - 48;
    float cc = cosT[s * 16 + j], ss = sinT[s * 16 + j];
    v = make_float2(v.x * cc - v.y * ss, v.x * ss + v.y * cc);
  }
  float hx = __bfloat162float(__float2bfloat16(v.x));
  float hy = __bfloat162float(__float2bfloat16(v.y));
  size_t dst = ((size_t)bh * SEQ + s) * HD + p * 2;
  *(uint32_t*)(Qh + dst) = pack2bf(v.x, v.y);
  *(uint32_t*)(Ql + dst) = pack2bf(v.x - hx, v.y - hy);
}

// ---------------- k prep: assemble + rope + split to [BH][SEQ][HD] ----------
// kvup row layout: [kn 0:1536 | kr 1536:2048 | v 2048:4096]
__global__ void k_prep_kernel(const float* __restrict__ kvup,
                              __nv_bfloat16* __restrict__ Kh,
                              __nv_bfloat16* __restrict__ Kl,
                              const float* __restrict__ cosT,
                              const float* __restrict__ sinT) {
  int idx = blockIdx.x * blockDim.x + threadIdx.x;  // BH*SEQ*64
  if (idx >= BH * SEQ * 64) return;
  int p = idx & 63;
  int s = (idx >> 6) & (SEQ - 1);
  int bh = idx >> 17;
  int b = bh >> 4, h = bh & 15;
  size_t tok = (size_t)(b * SEQ + s);
  float2 v;
  if (p < 48) {
    v = *(const float2*)(kvup + tok * KVUP + h * NOPE + p * 2);
  } else {
    int j = p - 48;
    float cc = cosT[s * 16 + j], ss = sinT[s * 16 + j];
    float2 r = *(const float2*)(kvup + tok * KVUP + QR + h * 32 + j * 2);
    v = make_float2(r.x * cc - r.y * ss, r.x * ss + r.y * cc);
  }
  float hx = __bfloat162float(__float2bfloat16(v.x));
  float hy = __bfloat162float(__float2bfloat16(v.y));
  size_t dst = ((size_t)bh * SEQ + s) * HD + p * 2;
  *(uint32_t*)(Kh + dst) = pack2bf(v.x, v.y);
  *(uint32_t*)(Kl + dst) = pack2bf(v.x - hx, v.y - hy);
}

// ---------------- v prep: transpose + split to [BH][HD][SEQ] ----------------
__global__ void vt_prep_kernel(const float* __restrict__ kvup,
                               __nv_bfloat16* __restrict__ Vh,
                               __nv_bfloat16* __restrict__ Vl) {
  __shared__ float t[32][33];
  int bh = blockIdx.z, b = bh >> 4, h = bh & 15;
  int s0 = blockIdx.x * 32, d0 = blockIdx.y * 32;
  int tx = threadIdx.x, ty = threadIdx.y;
#pragma unroll
  for (int i = 0; i < 32; i += 8)
    t[ty + i][tx] = kvup[((size_t)(b * SEQ) + s0 + ty + i) * KVUP + 2048 +
                         h * HD + d0 + tx];
  __syncthreads();
#pragma unroll
  for (int i = 0; i < 32; i += 8) {
    float val = t[tx][ty + i];
    size_t o = ((size_t)bh * HD + d0 + ty + i) * SEQ + s0 + tx;
    __nv_bfloat16 hh = __float2bfloat16(val);
    Vh[o] = hh;
    Vl[o] = __float2bfloat16(val - __bfloat162float(hh));
  }
}

// ---------------- tensor-core flash attention --------------------------------
#define FS_QL 17408
#define FS_K0 34816
#define FS_STG 35840
#define FS_KL 8704
#define FS_VH 17408
#define FLASH_MMA_SMEM 212992

__device__ __forceinline__ void flash_load_kv(
    uint32_t sb, const __nv_bfloat16* Kh, const __nv_bfloat16* Kl,
    const __nv_bfloat16* Vth, const __nv_bfloat16* Vtl, int kb, int stg,
    int tid) {
  uint32_t base = sb + (uint32_t)(FS_K0 + stg * FS_STG) * 2;
#pragma unroll
  for (int i = 0; i < 4; i++) {
    int idx = tid + i * 256;
    int r = idx >> 4, c = (idx & 15) << 3;
    uint32_t d = base + (uint32_t)(r * 136 + c) * 2;
    size_t gsrc = (size_t)(kb * 64 + r) * HD + c;
    cp16(d, Kh + gsrc);
    cp16(d + FS_KL * 2, Kl + gsrc);
  }
#pragma unroll
  for (int i = 0; i < 4; i++) {
    int idx = tid + i * 256;
    int r = idx >> 3, c = (idx & 7) << 3;
    uint32_t d = base + FS_VH * 2 + (uint32_t)(r * 72 + c) * 2;
    size_t gsrc = (size_t)r * SEQ + kb * 64 + c;
    cp16(d, Vth + gsrc);
    cp16(d + 9216 * 2, Vtl + gsrc);
  }
}

__global__ __launch_bounds__(256) void flash_mma_kernel(
    const __nv_bfloat16* __restrict__ Qh_, const __nv_bfloat16* __restrict__ Ql_,
    const __nv_bfloat16* __restrict__ Kh_, const __nv_bfloat16* __restrict__ Kl_,
    const __nv_bfloat16* __restrict__ Vh_, const __nv_bfloat16* __restrict__ Vl_,
    __nv_bfloat16* __restrict__ Oh, __nv_bfloat16* __restrict__ Ol) {
  extern __shared__ __nv_bfloat16 fs[];
  const uint32_t sb = smem_u32(fs);
  const int qb = gridDim.x - 1 - blockIdx.x;  // big tiles first
  const int bh = blockIdx.y;
  const int b = bh >> 4, h = bh & 15;
  const int tid = threadIdx.x, warp = tid >> 5, lane = tid & 31;
  const int g = lane >> 2, tg = lane & 3;
  const __nv_bfloat16* Qh = Qh_ + ((size_t)bh * SEQ + qb * 128) * HD;
  const __nv_bfloat16* Ql = Ql_ + ((size_t)bh * SEQ + qb * 128) * HD;
  const __nv_bfloat16* Kh = Kh_ + (size_t)bh * SEQ * HD;
  const __nv_bfloat16* Kl = Kl_ + (size_t)bh * SEQ * HD;
  const __nv_bfloat16* Vh = Vh_ + (size_t)bh * HD * SEQ;
  const __nv_bfloat16* Vl = Vl_ + (size_t)bh * HD * SEQ;

#pragma unroll
  for (int i = 0; i < 8; i++) {
    int idx = tid + i * 256;
    int r = idx >> 4, c = (idx & 15) << 3;
    uint32_t d = sb + (uint32_t)(r * 136 + c) * 2;
    cp16(d, Qh + (size_t)r * HD + c);
    cp16(d + FS_QL * 2, Ql + (size_t)r * HD + c);
  }
  flash_load_kv(sb, Kh, Kl, Vh, Vl, 0, 0, tid);
  cp_commit();

  float m0 = -1e30f, m1 = -1e30f, l0 = 0.f, l1 = 0.f;
  float o[16][4];
#pragma unroll
  for (int ni = 0; ni < 16; ni++)
#pragma unroll
    for (int k = 0; k < 4; k++) o[ni][k] = 0.f;

  const int nkb = 2 * qb + 2;
  const int rg0 = qb * 128 + warp * 16 + g;
  const int rg1 = rg0 + 8;
  const float scale = 0.08838834764831843f;

  for (int kb = 0; kb < nkb; kb++) {
    if (kb + 1 < nkb) {
      flash_load_kv(sb, Kh, Kl, Vh, Vl, kb + 1, (kb + 1) & 1, tid);
      cp_commit();
      asm volatile("cp.async.wait_group 1;" ::: "memory");
    } else {
      asm volatile("cp.async.wait_group 0;" ::: "memory");
    }
    __syncthreads();
    const __nv_bfloat16* Ks = fs + FS_K0 + (kb & 1) * FS_STG;
    const __nv_bfloat16* Vs = Ks + FS_VH;

    float c[8][4];
#pragma unroll
    for (int ni = 0; ni < 8; ni++)
#pragma unroll
      for (int k = 0; k < 4; k++) c[ni][k] = 0.f;
#pragma unroll
    for (int kk = 0; kk < 8; kk++) {
      const __nv_bfloat16* qp = fs + (warp * 16 + g) * 136 + kk * 16 + tg * 2;
      uint32_t ah[4], al[4];
      ah[0] = *(const uint32_t*)qp;
      ah[1] = *(const uint32_t*)(qp + 1088);
      ah[2] = *(const uint32_t*)(qp + 8);
      ah[3] = *(const uint32_t*)(qp + 1096);
      al[0] = *(const uint32_t*)(qp + FS_QL);
      al[1] = *(const uint32_t*)(qp + FS_QL + 1088);
      al[2] = *(const uint32_t*)(qp + FS_QL + 8);
      al[3] = *(const uint32_t*)(qp + FS_QL + 1096);
#pragma unroll
      for (int ni = 0; ni < 8; ni++) {
        const __nv_bfloat16* kp = Ks + (ni * 8 + g) * 136 + kk * 16 + tg * 2;
        uint32_t bh2[2], bl2[2];
        bh2[0] = *(const uint32_t*)kp;
        bh2[1] = *(const uint32_t*)(kp + 8);
        bl2[0] = *(const uint32_t*)(kp + FS_KL);
        bl2[1] = *(const uint32_t*)(kp + FS_KL + 8);
        mma16816(c[ni], ah, bh2);
        mma16816(c[ni], al, bh2);
        mma16816(c[ni], ah, bl2);
      }
    }

    const bool msk = (kb >= 2 * qb);
    float mx0 = -1e30f, mx1 = -1e30f;
#pragma unroll
    for (int ni = 0; ni < 8; ni++) {
      int cg = kb * 64 + ni * 8 + tg * 2;
      float t0 = c[ni][0] * scale, t1 = c[ni][1] * scale;
      float t2 = c[ni][2] * scale, t3 = c[ni][3] * scale;
      if (msk) {
        if (cg > rg0) t0 = -1e30f;
        if (cg + 1 > rg0) t1 = -1e30f;
        if (cg > rg1) t2 = -1e30f;
        if (cg + 1 > rg1) t3 = -1e30f;
      }
      c[ni][0] = t0; c[ni][1] = t1; c[ni][2] = t2; c[ni][3] = t3;
      mx0 = fmaxf(mx0, fmaxf(t0, t1));
      mx1 = fmaxf(mx1, fmaxf(t2, t3));
    }
    mx0 = fmaxf(mx0, __shfl_xor_sync(0xffffffffu, mx0, 1));
    mx0 = fmaxf(mx0, __shfl_xor_sync(0xffffffffu, mx0, 2));
    mx1 = fmaxf(mx1, __shfl_xor_sync(0xffffffffu, mx1, 1));
    mx1 = fmaxf(mx1, __shfl_xor_sync(0xffffffffu, mx1, 2));

    float mn0 = fmaxf(m0, mx0), mn1 = fmaxf(m1, mx1);
    float corr0 = __expf(m0 - mn0), corr1 = __expf(m1 - mn1);
    m0 = mn0; m1 = mn1;
    float s0 = 0.f, s1 = 0.f;
#pragma unroll
    for (int ni = 0; ni < 8; ni++) {
      c[ni][0] = __expf(c[ni][0] - mn0);
      c[ni][1] = __expf(c[ni][1] - mn0);
      c[ni][2] = __expf(c[ni][2] - mn1);
      c[ni][3] = __expf(c[ni][3] - mn1);
      s0 += c[ni][0] + c[ni][1];
      s1 += c[ni][2] + c[ni][3];
    }
    s0 += __shfl_xor_sync(0xffffffffu, s0, 1);
    s0 += __shfl_xor_sync(0xffffffffu, s0, 2);
    s1 += __shfl_xor_sync(0xffffffffu, s1, 1);
    s1 += __shfl_xor_sync(0xffffffffu, s1, 2);
    l0 = l0 * corr0 + s0;
    l1 = l1 * corr1 + s1;

#pragma unroll
    for (int ni = 0; ni < 16; ni++) {
      o[ni][0] *= corr0; o[ni][1] *= corr0;
      o[ni][2] *= corr1; o[ni][3] *= corr1;
    }

#pragma unroll
    for (int kc = 0; kc < 4; kc++) {
      float p00 = c[2 * kc][0], p01 = c[2 * kc][1];
      float p02 = c[2 * kc][2], p03 = c[2 * kc][3];
      float p10 = c[2 * kc + 1][0], p11 = c[2 * kc + 1][1];
      float p12 = c[2 * kc + 1][2], p13 = c[2 * kc + 1][3];
      uint32_t ap[4], apl[4];
      ap[0] = pack2bf(p00, p01);
      ap[1] = pack2bf(p02, p03);
      ap[2] = pack2bf(p10, p11);
      ap[3] = pack2bf(p12, p13);
      float h00 = __bfloat162float(__float2bfloat16(p00));
      float h01 = __bfloat162float(__float2bfloat16(p01));
      float h02 = __bfloat162float(__float2bfloat16(p02));
      float h03 = __bfloat162float(__float2bfloat16(p03));
      float h10 = __bfloat162float(__float2bfloat16(p10));
      float h11 = __bfloat162float(__float2bfloat16(p11));
      float h12 = __bfloat162float(__float2bfloat16(p12));
      float h13 = __bfloat162float(__float2bfloat16(p13));
      apl[0] = pack2bf(p00 - h00, p01 - h01);
      apl[1] = pack2bf(p02 - h02, p03 - h03);
      apl[2] = pack2bf(p10 - h10, p11 - h11);
      apl[3] = pack2bf(p12 - h12, p13 - h13);
#pragma unroll
      for (int ni = 0; ni < 16; ni++) {
        const __nv_bfloat16* vp = Vs + (ni * 8 + g) * 72 + kc * 16 + tg * 2;
        uint32_t bv[2], bvl[2];
        bv[0] = *(const uint32_t*)vp;
        bv[1] = *(const uint32_t*)(vp + 8);
        bvl[0] = *(const uint32_t*)(vp + 9216);
        bvl[1] = *(const uint32_t*)(vp + 9216 + 8);
        mma16816(o[ni], ap, bv);
        mma16816(o[ni], apl, bv);
        mma16816(o[ni], ap, bvl);
      }
    }
    __syncthreads();
  }

  const float inv0 = 1.f / l0, inv1 = 1.f / l1;
  const size_t row0 = (size_t)b * SEQ + qb * 128 + warp * 16 + g;
#pragma unroll
  for (int ni = 0; ni < 16; ni++) {
    int col = h * HD + ni * 8 + tg * 2;
    float v0 = o[ni][0] * inv0, v1 = o[ni][1] * inv0;
    float v2 = o[ni][2] * inv1, v3 = o[ni][3] * inv1;
    float h0 = __bfloat162float(__float2bfloat16(v0));
    float h1 = __bfloat162float(__float2bfloat16(v1));
    float h2 = __bfloat162float(__float2bfloat16(v2));
    float h3 = __bfloat162float(__float2bfloat16(v3));
    size_t i0 = row0 * HHD + col;
    size_t i1 = (row0 + 8) * HHD + col;
    *(uint32_t*)(Oh + i0) = pack2bf(v0, v1);
    *(uint32_t*)(Ol + i0) = pack2bf(v0 - h0, v1 - h1);
    *(uint32_t*)(Oh + i1) = pack2bf(v2, v3);
    *(uint32_t*)(Ol + i1) = pack2bf(v2 - h2, v3 - h3);
  }
}

// ---------------- launch -----------------------------------------------------
#define SYM(p, s)                          \
  do {                                     \
    void* _t;                              \
    cudaGetSymbolAddress(&_t, s);          \
    p = (decltype(p))_t;                   \
  } while (0)

extern "C" void kernel_launch(void* const* d_in, const int* in_sizes, int n_in,
                              void* d_out, int out_size) {
  const float* x = (const float*)d_in[0];
  const float* cosT = (const float*)d_in[1];
  const float* sinT = (const float*)d_in[2];
  const float* wq_down = (const float*)d_in[3];
  const float* wq_up = (const float*)d_in[4];
  const float* wkv_down = (const float*)d_in[5];
  const float* w_nope = (const float*)d_in[6];
  const float* w_rope = (const float*)d_in[7];
  const float* w_val = (const float*)d_in[8];
  const float* wo = (const float*)d_in[9];
  float* out = (float*)d_out;

  float *p_q, *p_kvup;
  SYM(p_q, g_q); SYM(p_kvup, g_kvup);

  __nv_bfloat16 *xh, *xl, *qkvh, *qkvl, *ath, *atl;
  __nv_bfloat16 *qah, *qal, *kah, *kal, *vth, *vtl;
  __nv_bfloat16 *wAh, *wAl, *wquh, *wqul, *wBh, *wBl, *woh, *wol;
  SYM(xh, g_x_h);   SYM(xl, g_x_l);
  SYM(qkvh, g_qkv_h); SYM(qkvl, g_qkv_l);
  SYM(ath, g_at_h); SYM(atl, g_at_l);
  SYM(qah, g_qa_h); SYM(qal, g_qa_l); SYM(kah, g_ka_h); SYM(kal, g_ka_l);
  SYM(vth, g_vt_h); SYM(vtl, g_vt_l);
  SYM(wAh, g_wA_h); SYM(wAl, g_wA_l); SYM(wquh, g_wqu_h); SYM(wqul, g_wqu_l);
  SYM(wBh, g_wB_h); SYM(wBl, g_wB_l); SYM(woh, g_wo_h);  SYM(wol, g_wo_l);

  cudaFuncSetAttribute(mma_gemm_kernel,
                       cudaFuncAttributeMaxDynamicSharedMemorySize, MG_SMEM);
  cudaFuncSetAttribute(flash_mma_kernel,
                       cudaFuncAttributeMaxDynamicSharedMemorySize,
                       FLASH_MMA_SMEM);

  dim3 tsb(32, 8);
  // input/weight conversions (wA = [wq_down | wkv_down], wB = [wn|wr|wv])
  split_kernel<<<(NT * DIM / 4) / 256, 256>>>(x, xh, xl, NT * DIM / 4);
  tsplit_kernel<<<dim3(QR / 32, DIM / 32), tsb>>>(wq_down, wAh, wAl, DIM, QR);
  tsplit_kernel<<<dim3(KVR / 32, DIM / 32), tsb>>>(
      wkv_down, wAh + (size_t)QR * DIM, wAl + (size_t)QR * DIM, DIM, KVR);
  tsplit_kernel<<<dim3(HHD / 32, QR / 32), tsb>>>(wq_up, wquh, wqul, QR, HHD);
  tsplit_kernel<<<dim3(QR / 32, KVR / 32), tsb>>>(w_nope, wBh, wBl, KVR, QR);
  tsplit_kernel<<<dim3(512 / 32, KVR / 32), tsb>>>(
      w_rope, wBh + (size_t)QR * KVR, wBl + (size_t)QR * KVR, KVR, 512);
  tsplit_kernel<<<dim3(HHD / 32, KVR / 32), tsb>>>(
      w_val, wBh + (size_t)2048 * KVR, wBl + (size_t)2048 * KVR, KVR, HHD);
  tsplit_kernel<<<dim3(DIM / 32, HHD / 32), tsb>>>(wo, woh, wol, HHD, DIM);

  // G1: x @ [wq_down|wkv_down] -> qkv hi/lo bf16 [NT, 2048]
  mma_gemm_kernel<<<dim3(2048 / 128, NT / 128), 256, MG_SMEM>>>(
      xh, xl, wAh, wAl, nullptr, qkvh, qkvl, 2048, DIM, DIM, DIM, 1);
  // G2: qlat @ wq_up -> p_q fp32
  mma_gemm_kernel<<<dim3(HHD / 128, NT / 128), 256, MG_SMEM>>>(
      qkvh, qkvl, wquh, wqul, p_q, nullptr, nullptr, HHD, QR, 2048, QR, 0);
  // G3: kv @ [wn|wr|wv] -> p_kvup fp32 [NT, 4096]
  mma_gemm_kernel<<<dim3(KVUP / 128, NT / 128), 256, MG_SMEM>>>(
      qkvh + QR, qkvl + QR, wBh, wBl, p_kvup, nullptr, nullptr, KVUP, KVR,
      2048, KVR, 0);

  // attention operand prep
  q_prep_kernel<<<(BH * SEQ * 64) / 256, 256>>>(p_q, qah, qal, cosT, sinT);
  k_prep_kernel<<<(BH * SEQ * 64) / 256, 256>>>(p_kvup, kah, kal, cosT, sinT);
  vt_prep_kernel<<<dim3(SEQ / 32, HD / 32, BH), tsb>>>(p_kvup, vth, vtl);

  // attention (writes bf16 hi/lo directly)
  flash_mma_kernel<<<dim3(SEQ / 128, BH), 256, FLASH_MMA_SMEM>>>(
      qah, qal, kah, kal, vth, vtl, ath, atl);

  // G4: attn @ wo -> out fp32
  mma_gemm_kernel<<<dim3(DIM / 128, NT / 128), 256, MG_SMEM>>>(
      ath, atl, woh, wol, out, nullptr, nullptr, DIM, HHD, HHD, HHD, 0);
}